// round 14
// baseline (speedup 1.0000x reference)
#include <cuda_runtime.h>
#include <cuda_bf16.h>
#include <cstdint>

#define NMAX 100000
#define EMAX 1600000
#define EPS 1e-5f

// ------------------- device scratch (no allocations allowed) -------------------
__device__ __nv_bfloat16 g_shi[(size_t)NMAX * 512];   // aggregated features, hi plane
__device__ __nv_bfloat16 g_slo[(size_t)NMAX * 512];   // aggregated features, lo plane
__device__ __nv_bfloat16 g_hhi[(size_t)NMAX * 128];   // activation hi plane (also x planes)
__device__ __nv_bfloat16 g_hlo[(size_t)NMAX * 128];   // activation lo plane
__device__ float g_preA[(size_t)NMAX * 128];          // pre-BN buffer (ping)
__device__ float g_preB[(size_t)NMAX * 128];          // pre-BN buffer (pong)
__device__ __nv_bfloat16 g_wimg[(size_t)54 * 8192];   // pre-swizzled weight chunk images (16KB each)
__device__ int   g_rowptr[NMAX + 1];
__device__ int   g_cursor[NMAX];
__device__ int   g_edges[EMAX];                       // packed (src<<2)|etype, sorted by dst
__device__ int   g_bsum[512];                         // per-block count sums for scan
__device__ float g_sums[4 * 128];                     // BN stats slots (one per layer)
__device__ float g_sumsq[4 * 128];

// ------------------- helpers -------------------
__device__ __forceinline__ uint32_t smem_u32(const void* p) {
    uint32_t a;
    asm("{ .reg .u64 t; cvta.to.shared.u64 t, %1; cvt.u32.u64 %0, t; }" : "=r"(a) : "l"(p));
    return a;
}
#define SW64(x) ((x) ^ (((x) >> 3) & 0x30))

#define LDSM_X4(r, addr) \
    asm volatile("ldmatrix.sync.aligned.m8n8.x4.shared.b16 {%0,%1,%2,%3}, [%4];" \
        : "=r"((r)[0]), "=r"((r)[1]), "=r"((r)[2]), "=r"((r)[3]) : "r"(addr))

#define MMA_BF16(d, a, b0v, b1v) \
    asm volatile("mma.sync.aligned.m16n8k16.row.col.f32.bf16.bf16.f32 " \
        "{%0,%1,%2,%3}, {%4,%5,%6,%7}, {%8,%9}, {%0,%1,%2,%3};" \
        : "+f"((d)[0]), "+f"((d)[1]), "+f"((d)[2]), "+f"((d)[3]) \
        : "r"((a)[0]), "r"((a)[1]), "r"((a)[2]), "r"((a)[3]), "r"(b0v), "r"(b1v))

#define CP16(dst, src) \
    asm volatile("cp.async.cg.shared.global [%0], [%1], 16;" :: "r"(dst), "l"(src) : "memory")
#define CP_COMMIT() asm volatile("cp.async.commit_group;" ::: "memory")
#define CP_WAIT1()  asm volatile("cp.async.wait_group 1;" ::: "memory")
#define CP_WAIT0()  asm volatile("cp.async.wait_group 0;" ::: "memory")

// hi/lo bf16 split of a float pair: packed u32 (low half = x, high half = y)
__device__ __forceinline__ void split2(float x, float y, uint32_t& hi, uint32_t& lo) {
    uint32_t h;
    asm("cvt.rn.bf16x2.f32 %0, %1, %2;" : "=r"(h) : "f"(y), "f"(x));
    float hx = __uint_as_float(h << 16);
    float hy = __uint_as_float(h & 0xFFFF0000u);
    float lx = x - hx, ly = y - hy;
    uint32_t l;
    asm("cvt.rn.bf16x2.f32 %0, %1, %2;" : "=r"(l) : "f"(ly), "f"(lx));
    hi = h; lo = l;
}

// ------------------- CSR build -------------------
__global__ void k_prep(int n) {
    int i = blockIdx.x * blockDim.x + threadIdx.x;
    if (i < n) g_cursor[i] = 0;
    if (i < 512) { g_sums[i] = 0.f; g_sumsq[i] = 0.f; }
}

__global__ void k_hist(const int* __restrict__ dst, int E) {
    int i = blockIdx.x * blockDim.x + threadIdx.x;
    if (i < E) atomicAdd(&g_cursor[dst[i]], 1);
}

__global__ void k_scan1(int n) {
    __shared__ int sh[256];
    int i = blockIdx.x * 256 + threadIdx.x;
    sh[threadIdx.x] = (i < n) ? g_cursor[i] : 0;
    __syncthreads();
    for (int off = 128; off > 0; off >>= 1) {
        if (threadIdx.x < off) sh[threadIdx.x] += sh[threadIdx.x + off];
        __syncthreads();
    }
    if (threadIdx.x == 0) g_bsum[blockIdx.x] = sh[0];
}

__global__ void k_scan3(int n) {
    __shared__ int sh[256];
    __shared__ int sc[256];
    int b = blockIdx.x, tid = threadIdx.x;
    int i = b * 256 + tid;
    int cp = 0;
    for (int j = tid; j < b; j += 256) cp += g_bsum[j];
    sc[tid] = cp;
    int v = (i < n) ? g_cursor[i] : 0;
    sh[tid] = v;
    __syncthreads();
    for (int off = 128; off > 0; off >>= 1) {
        if (tid < off) sc[tid] += sc[tid + off];
        __syncthreads();
    }
    int carry = sc[0];
    for (int off = 1; off < 256; off <<= 1) {
        int t = (tid >= off) ? sh[tid - off] : 0;
        __syncthreads();
        sh[tid] += t;
        __syncthreads();
    }
    int incl = sh[tid];
    if (i < n) {
        g_rowptr[i + 1] = carry + incl;
        g_cursor[i] = carry + incl - v;
    }
    if (b == 0 && tid == 0) g_rowptr[0] = 0;
}

__global__ void k_fill(const int* __restrict__ src, const int* __restrict__ dst,
                       const int* __restrict__ ety, int E) {
    int i = blockIdx.x * blockDim.x + threadIdx.x;
    if (i < E) {
        int pos = atomicAdd(&g_cursor[dst[i]], 1);
        g_edges[pos] = (src[i] << 2) | ety[i];
    }
}

// ------------------- weight images (SW64, 32-k chunks, fused all layers) -------------------
__global__ void k_wimg(const float* __restrict__ W0, const float* __restrict__ loop0,
                       const float* __restrict__ Ws, const float* __restrict__ loops,
                       const float* __restrict__ Wl, int total) {
    int t = blockIdx.x * blockDim.x + threadIdx.x;
    if (t >= total) return;                 // total = 54 * 2048
    int g = t >> 11;
    int rem = t & 2047;
    int ncol = rem >> 4;                    // 0..127
    int kp = rem & 15;                      // k pair 0..15
    const float *W1, *W2; int K1, lc;
    if (g < 10)      { W1 = W0; W2 = loop0; K1 = 256; lc = g; }
    else if (g < 30) { W1 = Ws; W2 = loops; K1 = 512; lc = g - 10; }
    else if (g < 50) { W1 = Ws + (size_t)4 * 128 * 128; W2 = loops + (size_t)128 * 128; K1 = 512; lc = g - 30; }
    else             { W1 = Wl; W2 = Wl; K1 = 128; lc = g - 50; }
    int kg = lc * 32 + kp * 2;
    const float* Wsrc; int krow;
    if (kg < K1) { Wsrc = W1; krow = kg; } else { Wsrc = W2; krow = kg - K1; }
    float w0 = __ldg(Wsrc + (size_t)krow * 128 + ncol);
    float w1 = __ldg(Wsrc + (size_t)(krow + 1) * 128 + ncol);
    uint32_t h, l;
    split2(w0, w1, h, l);
    uint32_t off = SW64((uint32_t)(ncol * 64 + kp * 4));
    char* cb = (char*)g_wimg + (size_t)g * 16384;
    *(uint32_t*)(cb + off) = h;
    *(uint32_t*)(cb + 8192 + off) = l;
}

// ------------------- x split (one-shot) -------------------
__global__ void k_splitx(const float* __restrict__ x, int total4) {
    int idx = blockIdx.x * blockDim.x + threadIdx.x;
    if (idx >= total4) return;
    float4 v = ((const float4*)x)[idx];
    uint32_t h01, l01, h23, l23;
    split2(v.x, v.y, h01, l01);
    split2(v.z, v.w, h23, l23);
    ((uint2*)g_hhi)[idx] = make_uint2(h01, h23);
    ((uint2*)g_hlo)[idx] = make_uint2(l01, l23);
}

// ------------------- aggregation (one warp per node, no atomics, node-range batched) -------------------
// layer0: raw x (F=64), unroll 4 for MLP
__global__ void k_agg64(const float* __restrict__ x, int n0, int n1) {
    int w = n0 + ((blockIdx.x * blockDim.x + threadIdx.x) >> 5);
    if (w >= n1) return;
    int lane = threadIdx.x & 31;
    int col = lane * 2;
    float2 a0 = make_float2(0.f, 0.f), a1 = a0, a2 = a0, a3 = a0;
    int e = g_rowptr[w], eend = g_rowptr[w + 1];
    for (; e + 4 <= eend; e += 4) {
        int pk0 = __ldg(&g_edges[e]);
        int pk1 = __ldg(&g_edges[e + 1]);
        int pk2 = __ldg(&g_edges[e + 2]);
        int pk3 = __ldg(&g_edges[e + 3]);
        float2 v0 = *(const float2*)(x + (size_t)(pk0 >> 2) * 64 + col);
        float2 v1 = *(const float2*)(x + (size_t)(pk1 >> 2) * 64 + col);
        float2 v2 = *(const float2*)(x + (size_t)(pk2 >> 2) * 64 + col);
        float2 v3 = *(const float2*)(x + (size_t)(pk3 >> 2) * 64 + col);
        int r;
        r = pk0 & 3;
        if (r == 0)      { a0.x += v0.x; a0.y += v0.y; }
        else if (r == 1) { a1.x += v0.x; a1.y += v0.y; }
        else if (r == 2) { a2.x += v0.x; a2.y += v0.y; }
        else             { a3.x += v0.x; a3.y += v0.y; }
        r = pk1 & 3;
        if (r == 0)      { a0.x += v1.x; a0.y += v1.y; }
        else if (r == 1) { a1.x += v1.x; a1.y += v1.y; }
        else if (r == 2) { a2.x += v1.x; a2.y += v1.y; }
        else             { a3.x += v1.x; a3.y += v1.y; }
        r = pk2 & 3;
        if (r == 0)      { a0.x += v2.x; a0.y += v2.y; }
        else if (r == 1) { a1.x += v2.x; a1.y += v2.y; }
        else if (r == 2) { a2.x += v2.x; a2.y += v2.y; }
        else             { a3.x += v2.x; a3.y += v2.y; }
        r = pk3 & 3;
        if (r == 0)      { a0.x += v3.x; a0.y += v3.y; }
        else if (r == 1) { a1.x += v3.x; a1.y += v3.y; }
        else if (r == 2) { a2.x += v3.x; a2.y += v3.y; }
        else             { a3.x += v3.x; a3.y += v3.y; }
    }
    for (; e < eend; ++e) {
        int pk = __ldg(&g_edges[e]);
        float2 v = *(const float2*)(x + (size_t)(pk >> 2) * 64 + col);
        int r = pk & 3;
        if (r == 0)      { a0.x += v.x; a0.y += v.y; }
        else if (r == 1) { a1.x += v.x; a1.y += v.y; }
        else if (r == 2) { a2.x += v.x; a2.y += v.y; }
        else             { a3.x += v.x; a3.y += v.y; }
    }
    size_t base = (size_t)w * 256 + col;
    float2 acc[4] = {a0, a1, a2, a3};
    #pragma unroll
    for (int r = 0; r < 4; ++r) {
        uint32_t h01, l01;
        split2(acc[r].x, acc[r].y, h01, l01);
        size_t bo = (base + r * 64) * 2;
        *(uint32_t*)((char*)g_shi + bo) = h01;
        *(uint32_t*)((char*)g_slo + bo) = l01;
    }
}

// hidden layers: gather from preIn with BN+ReLU inline (F=128), unroll 4.
// Also writes the node's own BN'd activation planes (merged k_bn_post).
// preIn is NOT written during this layer (ping-pong) -> batch-safe.
__global__ void k_agg128bn(const float* __restrict__ pre,
                           const float* __restrict__ gamma,
                           const float* __restrict__ beta,
                           int slot, float invN, int n0, int n1) {
    int w = n0 + ((blockIdx.x * blockDim.x + threadIdx.x) >> 5);
    if (w >= n1) return;
    int lane = threadIdx.x & 31;
    int col = lane * 4;
    float mu[4], sc[4], be[4];
    #pragma unroll
    for (int j = 0; j < 4; ++j) {
        int c = col + j;
        float s = g_sums[slot * 128 + c], q = g_sumsq[slot * 128 + c];
        float m = s * invN;
        float var = q * invN - m * m;
        mu[j] = m;
        sc[j] = __ldg(gamma + c) * rsqrtf(var + EPS);
        be[j] = __ldg(beta + c);
    }

    // self row: BN+ReLU+split -> activation planes (merged bn_post)
    {
        float4 v = *(const float4*)(pre + (size_t)w * 128 + col);
        float y0 = fmaxf((v.x - mu[0]) * sc[0] + be[0], 0.f);
        float y1 = fmaxf((v.y - mu[1]) * sc[1] + be[1], 0.f);
        float y2 = fmaxf((v.z - mu[2]) * sc[2] + be[2], 0.f);
        float y3 = fmaxf((v.w - mu[3]) * sc[3] + be[3], 0.f);
        uint32_t h01, l01, h23, l23;
        split2(y0, y1, h01, l01);
        split2(y2, y3, h23, l23);
        size_t ho = ((size_t)w * 128 + col) * 2;
        *(uint2*)((char*)g_hhi + ho) = make_uint2(h01, h23);
        *(uint2*)((char*)g_hlo + ho) = make_uint2(l01, l23);
    }

    float4 a0 = make_float4(0.f, 0.f, 0.f, 0.f), a1 = a0, a2 = a0, a3 = a0;
    int e = g_rowptr[w], eend = g_rowptr[w + 1];
    for (; e + 4 <= eend; e += 4) {
        int pk0 = __ldg(&g_edges[e]);
        int pk1 = __ldg(&g_edges[e + 1]);
        int pk2 = __ldg(&g_edges[e + 2]);
        int pk3 = __ldg(&g_edges[e + 3]);
        float4 v0 = *(const float4*)(pre + (size_t)(pk0 >> 2) * 128 + col);
        float4 v1 = *(const float4*)(pre + (size_t)(pk1 >> 2) * 128 + col);
        float4 v2 = *(const float4*)(pre + (size_t)(pk2 >> 2) * 128 + col);
        float4 v3 = *(const float4*)(pre + (size_t)(pk3 >> 2) * 128 + col);
        #pragma unroll
        for (int u = 0; u < 4; ++u) {
            float4 v = (u == 0) ? v0 : (u == 1) ? v1 : (u == 2) ? v2 : v3;
            int pk = (u == 0) ? pk0 : (u == 1) ? pk1 : (u == 2) ? pk2 : pk3;
            v.x = fmaxf((v.x - mu[0]) * sc[0] + be[0], 0.f);
            v.y = fmaxf((v.y - mu[1]) * sc[1] + be[1], 0.f);
            v.z = fmaxf((v.z - mu[2]) * sc[2] + be[2], 0.f);
            v.w = fmaxf((v.w - mu[3]) * sc[3] + be[3], 0.f);
            int r = pk & 3;
            if (r == 0)      { a0.x += v.x; a0.y += v.y; a0.z += v.z; a0.w += v.w; }
            else if (r == 1) { a1.x += v.x; a1.y += v.y; a1.z += v.z; a1.w += v.w; }
            else if (r == 2) { a2.x += v.x; a2.y += v.y; a2.z += v.z; a2.w += v.w; }
            else             { a3.x += v.x; a3.y += v.y; a3.z += v.z; a3.w += v.w; }
        }
    }
    for (; e < eend; ++e) {
        int pk = __ldg(&g_edges[e]);
        float4 v = *(const float4*)(pre + (size_t)(pk >> 2) * 128 + col);
        v.x = fmaxf((v.x - mu[0]) * sc[0] + be[0], 0.f);
        v.y = fmaxf((v.y - mu[1]) * sc[1] + be[1], 0.f);
        v.z = fmaxf((v.z - mu[2]) * sc[2] + be[2], 0.f);
        v.w = fmaxf((v.w - mu[3]) * sc[3] + be[3], 0.f);
        int r = pk & 3;
        if (r == 0)      { a0.x += v.x; a0.y += v.y; a0.z += v.z; a0.w += v.w; }
        else if (r == 1) { a1.x += v.x; a1.y += v.y; a1.z += v.z; a1.w += v.w; }
        else if (r == 2) { a2.x += v.x; a2.y += v.y; a2.z += v.z; a2.w += v.w; }
        else             { a3.x += v.x; a3.y += v.y; a3.z += v.z; a3.w += v.w; }
    }
    size_t base = (size_t)w * 512 + col;
    float4 acc[4] = {a0, a1, a2, a3};
    #pragma unroll
    for (int r = 0; r < 4; ++r) {
        uint32_t h01, l01, h23, l23;
        split2(acc[r].x, acc[r].y, h01, l01);
        split2(acc[r].z, acc[r].w, h23, l23);
        size_t bo = (base + r * 128) * 2;
        *(uint2*)((char*)g_shi + bo) = make_uint2(h01, h23);
        *(uint2*)((char*)g_slo + bo) = make_uint2(l01, l23);
    }
}

// ------------------- bf16-split GEMM, cp.async 2-stage pipeline (row-offset batched) -------------------
#define GEMM_SMEM 65536

__global__ void __launch_bounds__(256, 2)
k_gemm_mma(const char* __restrict__ A1h, const char* __restrict__ A1l, int K1,
           const char* __restrict__ A2h, const char* __restrict__ A2l, int K2,
           const char* __restrict__ wimg,
           const float* __restrict__ bias,
           float* __restrict__ C, int n, int m_base, int slot) {
    extern __shared__ char smem[];
    uint32_t sb = smem_u32(smem);
    int tid = threadIdx.x;
    int lane = tid & 31;
    int wid = tid >> 5;
    int wm = (wid & 1) * 64;
    int wn = (wid >> 1) * 32;
    int m0 = m_base + blockIdx.x * 128;
    int K = K1 + K2;
    int NC = K >> 5;

    uint32_t xorv = (uint32_t)(lane & 6) << 3;
    uint32_t colA = (uint32_t)(lane >> 4) * 16;
    uint32_t colB = (uint32_t)((lane >> 3) & 1) * 16;
    uint32_t rbA[4], rbB[2];
    #pragma unroll
    for (int i = 0; i < 4; ++i)
        rbA[i] = (uint32_t)(wm + (lane & 15) + i * 16) * 64;
    #pragma unroll
    for (int j = 0; j < 2; ++j)
        rbB[j] = (uint32_t)(wn + j * 16 + ((lane >> 4) << 3) + (lane & 7)) * 64;

    float acc[4][4][4];
    #pragma unroll
    for (int i = 0; i < 4; ++i)
        #pragma unroll
        for (int f = 0; f < 4; ++f)
            #pragma unroll
            for (int q = 0; q < 4; ++q) acc[i][f][q] = 0.f;

    auto stage = [&](int c, int buf) {
        int ck0 = c * 32;
        const char *ph, *pl; size_t rst, rofs;
        if (ck0 < K1) { ph = A1h; pl = A1l; rst = (size_t)K1 * 2; rofs = (size_t)ck0 * 2; }
        else          { ph = A2h; pl = A2l; rst = (size_t)K2 * 2; rofs = (size_t)(ck0 - K1) * 2; }
        uint32_t base = sb + buf * 32768;
        #pragma unroll
        for (int i = 0; i < 2; ++i) {
            int idx = i * 256 + tid;          // 0..511
            int row = idx >> 2;
            int seg = idx & 3;
            int grow = m0 + row; if (grow >= n) grow = n - 1;
            size_t so = (size_t)grow * rst + rofs + seg * 16;
            uint32_t d = base + SW64((uint32_t)(row * 64 + seg * 16));
            CP16(d, ph + so);
            CP16(d + 8192, pl + so);
        }
        const char* img = wimg + (size_t)c * 16384;
        #pragma unroll
        for (int i = 0; i < 2; ++i) {
            int idx = i * 256 + tid;
            CP16(base + 16384 + idx * 16, img + idx * 16);
            CP16(base + 24576 + idx * 16, img + 8192 + idx * 16);
        }
    };

    stage(0, 0);
    CP_COMMIT();
    for (int c = 0; c < NC; ++c) {
        if (c + 1 < NC) {
            stage(c + 1, (c + 1) & 1);
            CP_COMMIT();
            CP_WAIT1();
        } else {
            CP_WAIT0();
        }
        __syncthreads();
        uint32_t base = sb + (c & 1) * 32768;
        #pragma unroll
        for (int pass = 0; pass < 3; ++pass) {
            uint32_t Ab = base + (pass == 1 ? 8192 : 0);
            uint32_t Bb = base + 16384 + (pass == 2 ? 8192 : 0);
            #pragma unroll
            for (int kk = 0; kk < 2; ++kk) {
                uint32_t cA = (colA + (uint32_t)kk * 32) ^ xorv;
                uint32_t cB = (colB + (uint32_t)kk * 32) ^ xorv;
                uint32_t a[4][4], b[2][4];
                #pragma unroll
                for (int i = 0; i < 4; ++i) LDSM_X4(a[i], Ab + rbA[i] + cA);
                #pragma unroll
                for (int j = 0; j < 2; ++j) LDSM_X4(b[j], Bb + rbB[j] + cB);
                #pragma unroll
                for (int i = 0; i < 4; ++i) {
                    MMA_BF16(acc[i][0], a[i], b[0][0], b[0][1]);
                    MMA_BF16(acc[i][1], a[i], b[0][2], b[0][3]);
                    MMA_BF16(acc[i][2], a[i], b[1][0], b[1][1]);
                    MMA_BF16(acc[i][3], a[i], b[1][2], b[1][3]);
                }
            }
        }
        __syncthreads();
    }

    // ---- epilogue: bias add + store + fused BN stats ----
    float* s_sum = (float*)smem;     // [128]
    float* s_sq  = s_sum + 128;      // [128]
    if (tid < 128) { s_sum[tid] = 0.f; s_sq[tid] = 0.f; }
    __syncthreads();

    int g = lane >> 2, t = lane & 3;
    #pragma unroll
    for (int f = 0; f < 4; ++f) {
        int col = wn + f * 8 + t * 2;
        float bx = __ldg(bias + col), by = __ldg(bias + col + 1);
        float ls0 = 0.f, lq0 = 0.f, ls1 = 0.f, lq1 = 0.f;
        #pragma unroll
        for (int i = 0; i < 4; ++i) {
            int r0 = m0 + wm + i * 16 + g;
            if (r0 < n) {
                float y0 = acc[i][f][0] + bx, y1 = acc[i][f][1] + by;
                *(float2*)(C + (size_t)r0 * 128 + col) = make_float2(y0, y1);
                ls0 += y0; lq0 += y0 * y0; ls1 += y1; lq1 += y1 * y1;
            }
            int r1 = r0 + 8;
            if (r1 < n) {
                float y0 = acc[i][f][2] + bx, y1 = acc[i][f][3] + by;
                *(float2*)(C + (size_t)r1 * 128 + col) = make_float2(y0, y1);
                ls0 += y0; lq0 += y0 * y0; ls1 += y1; lq1 += y1 * y1;
            }
        }
        atomicAdd(&s_sum[col], ls0); atomicAdd(&s_sq[col], lq0);
        atomicAdd(&s_sum[col + 1], ls1); atomicAdd(&s_sq[col + 1], lq1);
    }
    __syncthreads();
    if (tid < 128) {
        atomicAdd(&g_sums[slot * 128 + tid], s_sum[tid]);
        atomicAdd(&g_sumsq[slot * 128 + tid], s_sq[tid]);
    }
}

// ------------------- BN post: planes and/or fp32 out -------------------
__global__ void k_bn_post(const float* __restrict__ pre,
                          const float* __restrict__ gamma,
                          const float* __restrict__ beta,
                          float* __restrict__ out,
                          __nv_bfloat16* __restrict__ phi,
                          __nv_bfloat16* __restrict__ plo,
                          int slot, int relu, float invN, int n) {
    int idx = blockIdx.x * blockDim.x + threadIdx.x;
    if (idx >= n * 32) return;
    int c4 = (idx & 31) * 4;
    float4 v = ((const float4*)pre)[idx];
    float y[4];
    #pragma unroll
    for (int j = 0; j < 4; j++) {
        int c = c4 + j;
        float mu = g_sums[slot * 128 + c] * invN;
        float var = g_sumsq[slot * 128 + c] * invN - mu * mu;
        float sc = __ldg(gamma + c) * rsqrtf(var + EPS);
        float be = __ldg(beta + c);
        float x = (j == 0) ? v.x : (j == 1) ? v.y : (j == 2) ? v.z : v.w;
        float yy = (x - mu) * sc + be;
        if (relu) yy = fmaxf(yy, 0.f);
        y[j] = yy;
    }
    if (out) ((float4*)out)[idx] = make_float4(y[0], y[1], y[2], y[3]);
    if (phi) {
        uint32_t h01, l01, h23, l23;
        split2(y[0], y[1], h01, l01);
        split2(y[2], y[3], h23, l23);
        ((uint2*)phi)[idx] = make_uint2(h01, h23);
        ((uint2*)plo)[idx] = make_uint2(l01, l23);
    }
}

// ------------------- launcher -------------------
extern "C" void kernel_launch(void* const* d_in, const int* in_sizes, int n_in,
                              void* d_out, int out_size) {
    const float* x     = (const float*)d_in[0];
    const int*   src   = (const int*)d_in[1];
    const int*   dst   = (const int*)d_in[2];
    const int*   ety   = (const int*)d_in[3];
    const float* W0    = (const float*)d_in[4];
    const float* loop0 = (const float*)d_in[5];
    const float* b0    = (const float*)d_in[6];
    const float* g0    = (const float*)d_in[7];
    const float* be0   = (const float*)d_in[8];
    const float* Ws    = (const float*)d_in[9];
    const float* loops = (const float*)d_in[10];
    const float* bs    = (const float*)d_in[11];
    const float* gs    = (const float*)d_in[12];
    const float* bes   = (const float*)d_in[13];
    const float* Wl    = (const float*)d_in[14];
    const float* bl    = (const float*)d_in[15];
    const float* gl    = (const float*)d_in[16];
    const float* bel   = (const float*)d_in[17];

    int N = in_sizes[0] / 64;
    int E = in_sizes[1];
    float* out = (float*)d_out;
    float invN = 1.0f / (float)N;

    float *preAP, *preBP;
    __nv_bfloat16 *shiP, *sloP, *hhiP, *hloP, *wimgP;
    cudaGetSymbolAddress((void**)&preAP, g_preA);
    cudaGetSymbolAddress((void**)&preBP, g_preB);
    cudaGetSymbolAddress((void**)&shiP, g_shi);
    cudaGetSymbolAddress((void**)&sloP, g_slo);
    cudaGetSymbolAddress((void**)&hhiP, g_hhi);
    cudaGetSymbolAddress((void**)&hloP, g_hlo);
    cudaGetSymbolAddress((void**)&wimgP, g_wimg);

    cudaFuncSetAttribute(k_gemm_mma, cudaFuncAttributeMaxDynamicSharedMemorySize, GEMM_SMEM);

    int tb = 256;
    int gE = (E + tb - 1) / tb;
    int gN = (N + tb - 1) / tb;
    int nb = (N + 255) / 256;
    int gV = (N * 32 + tb - 1) / tb;
    int tilesTotal = (N + 127) / 128;

    // --- CSR build (by dst), parallel scan ---
    k_prep<<<gN, tb>>>(N);
    k_hist<<<gE, tb>>>(dst, E);
    k_scan1<<<nb, 256>>>(N);
    k_scan3<<<nb, 256>>>(N);
    k_fill<<<gE, tb>>>(src, dst, ety, E);

    // --- weight images (all layers, one launch) + x planes ---
    k_wimg<<<(54 * 2048 + tb - 1) / tb, tb>>>(W0, loop0, Ws, loops, Wl, 54 * 2048);
    k_splitx<<<(N * 16 + tb - 1) / tb, tb>>>(x, N * 16);

    // --- layer 0: K = 256 (agg) + 64 (x planes), slot 0, 2 batches -> preA ---
    {
        int nBatch = 2;
        int tilesPer = (tilesTotal + nBatch - 1) / nBatch;
        for (int b = 0; b < nBatch; ++b) {
            int t0 = b * tilesPer;
            int t1 = min(tilesTotal, t0 + tilesPer);
            if (t0 >= t1) break;
            int n0 = t0 * 128;
            int n1 = min(N, t1 * 128);
            int gWb = ((n1 - n0) * 32 + tb - 1) / tb;
            k_agg64<<<gWb, tb>>>(x, n0, n1);
            k_gemm_mma<<<t1 - t0, tb, GEMM_SMEM>>>((const char*)shiP, (const char*)sloP, 256,
                                                   (const char*)hhiP, (const char*)hloP, 64,
                                                   (const char*)wimgP, b0, preAP, N, n0, 0);
        }
    }

    // --- hidden layers: K = 512 + 128, slots 1,2; 3 batches; ping-pong pre ---
    // l=0: read preA -> write preB ; l=1: read preB -> write preA
    for (int l = 0; l < 2; l++) {
        const float* gm = (l == 0) ? g0 : gs + (l - 1) * 128;
        const float* bt = (l == 0) ? be0 : bes + (l - 1) * 128;
        float* preIn  = (l == 0) ? preAP : preBP;
        float* preOut = (l == 0) ? preBP : preAP;
        int nBatch = 3;
        int tilesPer = (tilesTotal + nBatch - 1) / nBatch;
        for (int b = 0; b < nBatch; ++b) {
            int t0 = b * tilesPer;
            int t1 = min(tilesTotal, t0 + tilesPer);
            if (t0 >= t1) break;
            int n0 = t0 * 128;
            int n1 = min(N, t1 * 128);
            int gWb = ((n1 - n0) * 32 + tb - 1) / tb;
            k_agg128bn<<<gWb, tb>>>(preIn, gm, bt, l, invN, n0, n1);
            k_gemm_mma<<<t1 - t0, tb, GEMM_SMEM>>>((const char*)shiP, (const char*)sloP, 512,
                                                   (const char*)hhiP, (const char*)hloP, 128,
                                                   (const char*)wimgP + (size_t)(10 + l * 20) * 16384,
                                                   bs + l * 128, preOut, N, n0, l + 1);
        }
    }

    // --- final linear: hidden l=1 wrote preA (slot 2); final gemm -> preB (slot 3) ---
    k_bn_post<<<gV, tb>>>(preAP, gs + 128, bes + 128, (float*)nullptr, hhiP, hloP, 2, 1, invN, N);
    k_gemm_mma<<<tilesTotal, tb, GEMM_SMEM>>>((const char*)hhiP, (const char*)hloP, 128,
                                              (const char*)hhiP, (const char*)hloP, 0,
                                              (const char*)wimgP + (size_t)50 * 16384, bl, preBP, N, 0, 3);
    k_bn_post<<<gV, tb>>>(preBP, gl, bel, out, (__nv_bfloat16*)nullptr, (__nv_bfloat16*)nullptr,
                          3, 0, invN, N);
}

// round 15
// speedup vs baseline: 1.0571x; 1.0571x over previous
#include <cuda_runtime.h>
#include <cuda_bf16.h>
#include <cstdint>

#define NMAX 100000
#define EMAX 1600000
#define EPS 1e-5f

// ------------------- device scratch (no allocations allowed) -------------------
__device__ __nv_bfloat16 g_shi[(size_t)NMAX * 512];   // aggregated features, hi plane
__device__ __nv_bfloat16 g_slo[(size_t)NMAX * 512];   // aggregated features, lo plane
__device__ __nv_bfloat16 g_hhi[(size_t)NMAX * 128];   // activation hi plane (also x planes)
__device__ __nv_bfloat16 g_hlo[(size_t)NMAX * 128];   // activation lo plane
__device__ float g_pre[(size_t)NMAX * 128];           // pre-BN buffer
__device__ __nv_bfloat16 g_wimg[(size_t)54 * 8192];   // pre-swizzled weight chunk images (16KB each)
__device__ int   g_rowptr[NMAX + 1];
__device__ int   g_cursor[NMAX];
__device__ int   g_edges[EMAX];                       // packed (src<<2)|etype, sorted by dst
__device__ int   g_bsum[512];                         // per-block count sums for scan
__device__ float g_sums[4 * 128];                     // BN stats slots (one per layer)
__device__ float g_sumsq[4 * 128];

// ------------------- helpers -------------------
__device__ __forceinline__ uint32_t smem_u32(const void* p) {
    uint32_t a;
    asm("{ .reg .u64 t; cvta.to.shared.u64 t, %1; cvt.u32.u64 %0, t; }" : "=r"(a) : "l"(p));
    return a;
}
#define SW64(x) ((x) ^ (((x) >> 3) & 0x30))

#define LDSM_X4(r, addr) \
    asm volatile("ldmatrix.sync.aligned.m8n8.x4.shared.b16 {%0,%1,%2,%3}, [%4];" \
        : "=r"((r)[0]), "=r"((r)[1]), "=r"((r)[2]), "=r"((r)[3]) : "r"(addr))

#define MMA_BF16(d, a, b0v, b1v) \
    asm volatile("mma.sync.aligned.m16n8k16.row.col.f32.bf16.bf16.f32 " \
        "{%0,%1,%2,%3}, {%4,%5,%6,%7}, {%8,%9}, {%0,%1,%2,%3};" \
        : "+f"((d)[0]), "+f"((d)[1]), "+f"((d)[2]), "+f"((d)[3]) \
        : "r"((a)[0]), "r"((a)[1]), "r"((a)[2]), "r"((a)[3]), "r"(b0v), "r"(b1v))

#define CP16(dst, src) \
    asm volatile("cp.async.cg.shared.global [%0], [%1], 16;" :: "r"(dst), "l"(src) : "memory")
#define CP_COMMIT() asm volatile("cp.async.commit_group;" ::: "memory")
#define CP_WAIT1()  asm volatile("cp.async.wait_group 1;" ::: "memory")
#define CP_WAIT0()  asm volatile("cp.async.wait_group 0;" ::: "memory")

// hi/lo bf16 split of a float pair: packed u32 (low half = x, high half = y)
__device__ __forceinline__ void split2(float x, float y, uint32_t& hi, uint32_t& lo) {
    uint32_t h;
    asm("cvt.rn.bf16x2.f32 %0, %1, %2;" : "=r"(h) : "f"(y), "f"(x));
    float hx = __uint_as_float(h << 16);
    float hy = __uint_as_float(h & 0xFFFF0000u);
    float lx = x - hx, ly = y - hy;
    uint32_t l;
    asm("cvt.rn.bf16x2.f32 %0, %1, %2;" : "=r"(l) : "f"(ly), "f"(lx));
    hi = h; lo = l;
}

// ------------------- CSR build -------------------
__global__ void k_prep(int n) {
    int i = blockIdx.x * blockDim.x + threadIdx.x;
    if (i < n) g_cursor[i] = 0;
    if (i < 512) { g_sums[i] = 0.f; g_sumsq[i] = 0.f; }
}

__global__ void k_hist(const int* __restrict__ dst, int E) {
    int i = blockIdx.x * blockDim.x + threadIdx.x;
    if (i < E) atomicAdd(&g_cursor[dst[i]], 1);
}

__global__ void k_scan1(int n) {
    __shared__ int sh[256];
    int i = blockIdx.x * 256 + threadIdx.x;
    sh[threadIdx.x] = (i < n) ? g_cursor[i] : 0;
    __syncthreads();
    for (int off = 128; off > 0; off >>= 1) {
        if (threadIdx.x < off) sh[threadIdx.x] += sh[threadIdx.x + off];
        __syncthreads();
    }
    if (threadIdx.x == 0) g_bsum[blockIdx.x] = sh[0];
}

__global__ void k_scan3(int n) {
    __shared__ int sh[256];
    __shared__ int sc[256];
    int b = blockIdx.x, tid = threadIdx.x;
    int i = b * 256 + tid;
    int cp = 0;
    for (int j = tid; j < b; j += 256) cp += g_bsum[j];
    sc[tid] = cp;
    int v = (i < n) ? g_cursor[i] : 0;
    sh[tid] = v;
    __syncthreads();
    for (int off = 128; off > 0; off >>= 1) {
        if (tid < off) sc[tid] += sc[tid + off];
        __syncthreads();
    }
    int carry = sc[0];
    for (int off = 1; off < 256; off <<= 1) {
        int t = (tid >= off) ? sh[tid - off] : 0;
        __syncthreads();
        sh[tid] += t;
        __syncthreads();
    }
    int incl = sh[tid];
    if (i < n) {
        g_rowptr[i + 1] = carry + incl;
        g_cursor[i] = carry + incl - v;
    }
    if (b == 0 && tid == 0) g_rowptr[0] = 0;
}

__global__ void k_fill(const int* __restrict__ src, const int* __restrict__ dst,
                       const int* __restrict__ ety, int E) {
    int i = blockIdx.x * blockDim.x + threadIdx.x;
    if (i < E) {
        int pos = atomicAdd(&g_cursor[dst[i]], 1);
        g_edges[pos] = (src[i] << 2) | ety[i];
    }
}

// ------------------- weight images (SW64, 32-k chunks, fused all layers) -------------------
__global__ void k_wimg(const float* __restrict__ W0, const float* __restrict__ loop0,
                       const float* __restrict__ Ws, const float* __restrict__ loops,
                       const float* __restrict__ Wl, int total) {
    int t = blockIdx.x * blockDim.x + threadIdx.x;
    if (t >= total) return;                 // total = 54 * 2048
    int g = t >> 11;
    int rem = t & 2047;
    int ncol = rem >> 4;                    // 0..127
    int kp = rem & 15;                      // k pair 0..15
    const float *W1, *W2; int K1, lc;
    if (g < 10)      { W1 = W0; W2 = loop0; K1 = 256; lc = g; }
    else if (g < 30) { W1 = Ws; W2 = loops; K1 = 512; lc = g - 10; }
    else if (g < 50) { W1 = Ws + (size_t)4 * 128 * 128; W2 = loops + (size_t)128 * 128; K1 = 512; lc = g - 30; }
    else             { W1 = Wl; W2 = Wl; K1 = 128; lc = g - 50; }
    int kg = lc * 32 + kp * 2;
    const float* Wsrc; int krow;
    if (kg < K1) { Wsrc = W1; krow = kg; } else { Wsrc = W2; krow = kg - K1; }
    float w0 = __ldg(Wsrc + (size_t)krow * 128 + ncol);
    float w1 = __ldg(Wsrc + (size_t)(krow + 1) * 128 + ncol);
    uint32_t h, l;
    split2(w0, w1, h, l);
    uint32_t off = SW64((uint32_t)(ncol * 64 + kp * 4));
    char* cb = (char*)g_wimg + (size_t)g * 16384;
    *(uint32_t*)(cb + off) = h;
    *(uint32_t*)(cb + 8192 + off) = l;
}

// ------------------- x split (one-shot) -------------------
__global__ void k_splitx(const float* __restrict__ x, int total4) {
    int idx = blockIdx.x * blockDim.x + threadIdx.x;
    if (idx >= total4) return;
    float4 v = ((const float4*)x)[idx];
    uint32_t h01, l01, h23, l23;
    split2(v.x, v.y, h01, l01);
    split2(v.z, v.w, h23, l23);
    ((uint2*)g_hhi)[idx] = make_uint2(h01, h23);
    ((uint2*)g_hlo)[idx] = make_uint2(l01, l23);
}

// ------------------- aggregation (one warp per node, no atomics) -------------------
// layer0: raw x (F=64), unroll 4 for MLP
__global__ void k_agg64(const float* __restrict__ x, int N) {
    int w = (blockIdx.x * blockDim.x + threadIdx.x) >> 5;
    if (w >= N) return;
    int lane = threadIdx.x & 31;
    int col = lane * 2;
    float2 a0 = make_float2(0.f, 0.f), a1 = a0, a2 = a0, a3 = a0;
    int e = g_rowptr[w], eend = g_rowptr[w + 1];
    for (; e + 4 <= eend; e += 4) {
        int pk0 = __ldg(&g_edges[e]);
        int pk1 = __ldg(&g_edges[e + 1]);
        int pk2 = __ldg(&g_edges[e + 2]);
        int pk3 = __ldg(&g_edges[e + 3]);
        float2 v0 = *(const float2*)(x + (size_t)(pk0 >> 2) * 64 + col);
        float2 v1 = *(const float2*)(x + (size_t)(pk1 >> 2) * 64 + col);
        float2 v2 = *(const float2*)(x + (size_t)(pk2 >> 2) * 64 + col);
        float2 v3 = *(const float2*)(x + (size_t)(pk3 >> 2) * 64 + col);
        int r;
        r = pk0 & 3;
        if (r == 0)      { a0.x += v0.x; a0.y += v0.y; }
        else if (r == 1) { a1.x += v0.x; a1.y += v0.y; }
        else if (r == 2) { a2.x += v0.x; a2.y += v0.y; }
        else             { a3.x += v0.x; a3.y += v0.y; }
        r = pk1 & 3;
        if (r == 0)      { a0.x += v1.x; a0.y += v1.y; }
        else if (r == 1) { a1.x += v1.x; a1.y += v1.y; }
        else if (r == 2) { a2.x += v1.x; a2.y += v1.y; }
        else             { a3.x += v1.x; a3.y += v1.y; }
        r = pk2 & 3;
        if (r == 0)      { a0.x += v2.x; a0.y += v2.y; }
        else if (r == 1) { a1.x += v2.x; a1.y += v2.y; }
        else if (r == 2) { a2.x += v2.x; a2.y += v2.y; }
        else             { a3.x += v2.x; a3.y += v2.y; }
        r = pk3 & 3;
        if (r == 0)      { a0.x += v3.x; a0.y += v3.y; }
        else if (r == 1) { a1.x += v3.x; a1.y += v3.y; }
        else if (r == 2) { a2.x += v3.x; a2.y += v3.y; }
        else             { a3.x += v3.x; a3.y += v3.y; }
    }
    for (; e < eend; ++e) {
        int pk = __ldg(&g_edges[e]);
        float2 v = *(const float2*)(x + (size_t)(pk >> 2) * 64 + col);
        int r = pk & 3;
        if (r == 0)      { a0.x += v.x; a0.y += v.y; }
        else if (r == 1) { a1.x += v.x; a1.y += v.y; }
        else if (r == 2) { a2.x += v.x; a2.y += v.y; }
        else             { a3.x += v.x; a3.y += v.y; }
    }
    size_t base = (size_t)w * 256 + col;
    float2 acc[4] = {a0, a1, a2, a3};
    #pragma unroll
    for (int r = 0; r < 4; ++r) {
        uint32_t h01, l01;
        split2(acc[r].x, acc[r].y, h01, l01);
        size_t bo = (base + r * 64) * 2;
        *(uint32_t*)((char*)g_shi + bo) = h01;
        *(uint32_t*)((char*)g_slo + bo) = l01;
    }
}

// hidden layers: gather from g_pre with BN+ReLU inline (F=128), unroll 8.
// Also writes the node's own BN'd activation planes (merged k_bn_post).
__global__ void k_agg128bn(const float* __restrict__ pre,
                           const float* __restrict__ gamma,
                           const float* __restrict__ beta,
                           int slot, float invN, int N) {
    int w = (blockIdx.x * blockDim.x + threadIdx.x) >> 5;
    if (w >= N) return;
    int lane = threadIdx.x & 31;
    int col = lane * 4;
    float mu[4], sc[4], be[4];
    #pragma unroll
    for (int j = 0; j < 4; ++j) {
        int c = col + j;
        float s = g_sums[slot * 128 + c], q = g_sumsq[slot * 128 + c];
        float m = s * invN;
        float var = q * invN - m * m;
        mu[j] = m;
        sc[j] = __ldg(gamma + c) * rsqrtf(var + EPS);
        be[j] = __ldg(beta + c);
    }

    // self row: BN+ReLU+split -> activation planes (merged bn_post)
    {
        float4 v = *(const float4*)(pre + (size_t)w * 128 + col);
        float y0 = fmaxf((v.x - mu[0]) * sc[0] + be[0], 0.f);
        float y1 = fmaxf((v.y - mu[1]) * sc[1] + be[1], 0.f);
        float y2 = fmaxf((v.z - mu[2]) * sc[2] + be[2], 0.f);
        float y3 = fmaxf((v.w - mu[3]) * sc[3] + be[3], 0.f);
        uint32_t h01, l01, h23, l23;
        split2(y0, y1, h01, l01);
        split2(y2, y3, h23, l23);
        size_t ho = ((size_t)w * 128 + col) * 2;
        *(uint2*)((char*)g_hhi + ho) = make_uint2(h01, h23);
        *(uint2*)((char*)g_hlo + ho) = make_uint2(l01, l23);
    }

    float4 a0 = make_float4(0.f, 0.f, 0.f, 0.f), a1 = a0, a2 = a0, a3 = a0;
    int e = g_rowptr[w], eend = g_rowptr[w + 1];
    for (; e + 8 <= eend; e += 8) {
        int pk[8];
        #pragma unroll
        for (int u = 0; u < 8; ++u) pk[u] = __ldg(&g_edges[e + u]);
        float4 vv[8];
        #pragma unroll
        for (int u = 0; u < 8; ++u)
            vv[u] = *(const float4*)(pre + (size_t)(pk[u] >> 2) * 128 + col);
        #pragma unroll
        for (int u = 0; u < 8; ++u) {
            float4 v = vv[u];
            v.x = fmaxf((v.x - mu[0]) * sc[0] + be[0], 0.f);
            v.y = fmaxf((v.y - mu[1]) * sc[1] + be[1], 0.f);
            v.z = fmaxf((v.z - mu[2]) * sc[2] + be[2], 0.f);
            v.w = fmaxf((v.w - mu[3]) * sc[3] + be[3], 0.f);
            int r = pk[u] & 3;
            if (r == 0)      { a0.x += v.x; a0.y += v.y; a0.z += v.z; a0.w += v.w; }
            else if (r == 1) { a1.x += v.x; a1.y += v.y; a1.z += v.z; a1.w += v.w; }
            else if (r == 2) { a2.x += v.x; a2.y += v.y; a2.z += v.z; a2.w += v.w; }
            else             { a3.x += v.x; a3.y += v.y; a3.z += v.z; a3.w += v.w; }
        }
    }
    for (; e < eend; ++e) {
        int pk = __ldg(&g_edges[e]);
        float4 v = *(const float4*)(pre + (size_t)(pk >> 2) * 128 + col);
        v.x = fmaxf((v.x - mu[0]) * sc[0] + be[0], 0.f);
        v.y = fmaxf((v.y - mu[1]) * sc[1] + be[1], 0.f);
        v.z = fmaxf((v.z - mu[2]) * sc[2] + be[2], 0.f);
        v.w = fmaxf((v.w - mu[3]) * sc[3] + be[3], 0.f);
        int r = pk & 3;
        if (r == 0)      { a0.x += v.x; a0.y += v.y; a0.z += v.z; a0.w += v.w; }
        else if (r == 1) { a1.x += v.x; a1.y += v.y; a1.z += v.z; a1.w += v.w; }
        else if (r == 2) { a2.x += v.x; a2.y += v.y; a2.z += v.z; a2.w += v.w; }
        else             { a3.x += v.x; a3.y += v.y; a3.z += v.z; a3.w += v.w; }
    }
    size_t base = (size_t)w * 512 + col;
    float4 acc[4] = {a0, a1, a2, a3};
    #pragma unroll
    for (int r = 0; r < 4; ++r) {
        uint32_t h01, l01, h23, l23;
        split2(acc[r].x, acc[r].y, h01, l01);
        split2(acc[r].z, acc[r].w, h23, l23);
        size_t bo = (base + r * 128) * 2;
        *(uint2*)((char*)g_shi + bo) = make_uint2(h01, h23);
        *(uint2*)((char*)g_slo + bo) = make_uint2(l01, l23);
    }
}

// ------------------- bf16-split GEMM, cp.async 2-stage pipeline -------------------
// Inner loop restructured for fragment reuse: per k-step load Ah+Bh (MMA),
// Bl (MMA, reuse Ah), Al+Bh (MMA) -> 28 LDSM/chunk vs 36.
#define GEMM_SMEM 65536

__global__ void __launch_bounds__(256, 2)
k_gemm_mma(const char* __restrict__ A1h, const char* __restrict__ A1l, int K1,
           const char* __restrict__ A2h, const char* __restrict__ A2l, int K2,
           const char* __restrict__ wimg,
           const float* __restrict__ bias,
           float* __restrict__ C, int n, int slot) {
    extern __shared__ char smem[];
    uint32_t sb = smem_u32(smem);
    int tid = threadIdx.x;
    int lane = tid & 31;
    int wid = tid >> 5;
    int wm = (wid & 1) * 64;
    int wn = (wid >> 1) * 32;
    int m0 = blockIdx.x * 128;
    int K = K1 + K2;
    int NC = K >> 5;

    uint32_t xorv = (uint32_t)(lane & 6) << 3;
    uint32_t colA = (uint32_t)(lane >> 4) * 16;
    uint32_t colB = (uint32_t)((lane >> 3) & 1) * 16;
    uint32_t rbA[4], rbB[2];
    #pragma unroll
    for (int i = 0; i < 4; ++i)
        rbA[i] = (uint32_t)(wm + (lane & 15) + i * 16) * 64;
    #pragma unroll
    for (int j = 0; j < 2; ++j)
        rbB[j] = (uint32_t)(wn + j * 16 + ((lane >> 4) << 3) + (lane & 7)) * 64;

    float acc[4][4][4];
    #pragma unroll
    for (int i = 0; i < 4; ++i)
        #pragma unroll
        for (int f = 0; f < 4; ++f)
            #pragma unroll
            for (int q = 0; q < 4; ++q) acc[i][f][q] = 0.f;

    auto stage = [&](int c, int buf) {
        int ck0 = c * 32;
        const char *ph, *pl; size_t rst, rofs;
        if (ck0 < K1) { ph = A1h; pl = A1l; rst = (size_t)K1 * 2; rofs = (size_t)ck0 * 2; }
        else          { ph = A2h; pl = A2l; rst = (size_t)K2 * 2; rofs = (size_t)(ck0 - K1) * 2; }
        uint32_t base = sb + buf * 32768;
        #pragma unroll
        for (int i = 0; i < 2; ++i) {
            int idx = i * 256 + tid;          // 0..511
            int row = idx >> 2;
            int seg = idx & 3;
            int grow = m0 + row; if (grow >= n) grow = n - 1;
            size_t so = (size_t)grow * rst + rofs + seg * 16;
            uint32_t d = base + SW64((uint32_t)(row * 64 + seg * 16));
            CP16(d, ph + so);
            CP16(d + 8192, pl + so);
        }
        const char* img = wimg + (size_t)c * 16384;
        #pragma unroll
        for (int i = 0; i < 2; ++i) {
            int idx = i * 256 + tid;
            CP16(base + 16384 + idx * 16, img + idx * 16);
            CP16(base + 24576 + idx * 16, img + 8192 + idx * 16);
        }
    };

    stage(0, 0);
    CP_COMMIT();
    for (int c = 0; c < NC; ++c) {
        if (c + 1 < NC) {
            stage(c + 1, (c + 1) & 1);
            CP_COMMIT();
            CP_WAIT1();
        } else {
            CP_WAIT0();
        }
        __syncthreads();
        uint32_t base = sb + (c & 1) * 32768;
        uint32_t Ah = base, Al = base + 8192, Bh = base + 16384, Bl = base + 24576;
        #pragma unroll
        for (int kk = 0; kk < 2; ++kk) {
            uint32_t cA = (colA + (uint32_t)kk * 32) ^ xorv;
            uint32_t cB = (colB + (uint32_t)kk * 32) ^ xorv;
            uint32_t a[4][4], b[2][4];
            // pass 1: Ah * Bh
            #pragma unroll
            for (int i = 0; i < 4; ++i) LDSM_X4(a[i], Ah + rbA[i] + cA);
            #pragma unroll
            for (int j = 0; j < 2; ++j) LDSM_X4(b[j], Bh + rbB[j] + cB);
            #pragma unroll
            for (int i = 0; i < 4; ++i) {
                MMA_BF16(acc[i][0], a[i], b[0][0], b[0][1]);
                MMA_BF16(acc[i][1], a[i], b[0][2], b[0][3]);
                MMA_BF16(acc[i][2], a[i], b[1][0], b[1][1]);
                MMA_BF16(acc[i][3], a[i], b[1][2], b[1][3]);
            }
            // pass 2: Ah * Bl (reuse a)
            #pragma unroll
            for (int j = 0; j < 2; ++j) LDSM_X4(b[j], Bl + rbB[j] + cB);
            #pragma unroll
            for (int i = 0; i < 4; ++i) {
                MMA_BF16(acc[i][0], a[i], b[0][0], b[0][1]);
                MMA_BF16(acc[i][1], a[i], b[0][2], b[0][3]);
                MMA_BF16(acc[i][2], a[i], b[1][0], b[1][1]);
                MMA_BF16(acc[i][3], a[i], b[1][2], b[1][3]);
            }
            // pass 3: Al * Bh
            #pragma unroll
            for (int i = 0; i < 4; ++i) LDSM_X4(a[i], Al + rbA[i] + cA);
            #pragma unroll
            for (int j = 0; j < 2; ++j) LDSM_X4(b[j], Bh + rbB[j] + cB);
            #pragma unroll
            for (int i = 0; i < 4; ++i) {
                MMA_BF16(acc[i][0], a[i], b[0][0], b[0][1]);
                MMA_BF16(acc[i][1], a[i], b[0][2], b[0][3]);
                MMA_BF16(acc[i][2], a[i], b[1][0], b[1][1]);
                MMA_BF16(acc[i][3], a[i], b[1][2], b[1][3]);
            }
        }
        __syncthreads();
    }

    // ---- epilogue: bias add + store + fused BN stats ----
    float* s_sum = (float*)smem;     // [128]
    float* s_sq  = s_sum + 128;      // [128]
    if (tid < 128) { s_sum[tid] = 0.f; s_sq[tid] = 0.f; }
    __syncthreads();

    int g = lane >> 2, t = lane & 3;
    #pragma unroll
    for (int f = 0; f < 4; ++f) {
        int col = wn + f * 8 + t * 2;
        float bx = __ldg(bias + col), by = __ldg(bias + col + 1);
        float ls0 = 0.f, lq0 = 0.f, ls1 = 0.f, lq1 = 0.f;
        #pragma unroll
        for (int i = 0; i < 4; ++i) {
            int r0 = m0 + wm + i * 16 + g;
            if (r0 < n) {
                float y0 = acc[i][f][0] + bx, y1 = acc[i][f][1] + by;
                *(float2*)(C + (size_t)r0 * 128 + col) = make_float2(y0, y1);
                ls0 += y0; lq0 += y0 * y0; ls1 += y1; lq1 += y1 * y1;
            }
            int r1 = r0 + 8;
            if (r1 < n) {
                float y0 = acc[i][f][2] + bx, y1 = acc[i][f][3] + by;
                *(float2*)(C + (size_t)r1 * 128 + col) = make_float2(y0, y1);
                ls0 += y0; lq0 += y0 * y0; ls1 += y1; lq1 += y1 * y1;
            }
        }
        atomicAdd(&s_sum[col], ls0); atomicAdd(&s_sq[col], lq0);
        atomicAdd(&s_sum[col + 1], ls1); atomicAdd(&s_sq[col + 1], lq1);
    }
    __syncthreads();
    if (tid < 128) {
        atomicAdd(&g_sums[slot * 128 + tid], s_sum[tid]);
        atomicAdd(&g_sumsq[slot * 128 + tid], s_sq[tid]);
    }
}

// ------------------- BN post: planes and/or fp32 out -------------------
__global__ void k_bn_post(const float* __restrict__ pre,
                          const float* __restrict__ gamma,
                          const float* __restrict__ beta,
                          float* __restrict__ out,
                          __nv_bfloat16* __restrict__ phi,
                          __nv_bfloat16* __restrict__ plo,
                          int slot, int relu, float invN, int n) {
    int idx = blockIdx.x * blockDim.x + threadIdx.x;
    if (idx >= n * 32) return;
    int c4 = (idx & 31) * 4;
    float4 v = ((const float4*)pre)[idx];
    float y[4];
    #pragma unroll
    for (int j = 0; j < 4; j++) {
        int c = c4 + j;
        float mu = g_sums[slot * 128 + c] * invN;
        float var = g_sumsq[slot * 128 + c] * invN - mu * mu;
        float sc = __ldg(gamma + c) * rsqrtf(var + EPS);
        float be = __ldg(beta + c);
        float x = (j == 0) ? v.x : (j == 1) ? v.y : (j == 2) ? v.z : v.w;
        float yy = (x - mu) * sc + be;
        if (relu) yy = fmaxf(yy, 0.f);
        y[j] = yy;
    }
    if (out) ((float4*)out)[idx] = make_float4(y[0], y[1], y[2], y[3]);
    if (phi) {
        uint32_t h01, l01, h23, l23;
        split2(y[0], y[1], h01, l01);
        split2(y[2], y[3], h23, l23);
        ((uint2*)phi)[idx] = make_uint2(h01, h23);
        ((uint2*)plo)[idx] = make_uint2(l01, l23);
    }
}

// ------------------- launcher -------------------
extern "C" void kernel_launch(void* const* d_in, const int* in_sizes, int n_in,
                              void* d_out, int out_size) {
    const float* x     = (const float*)d_in[0];
    const int*   src   = (const int*)d_in[1];
    const int*   dst   = (const int*)d_in[2];
    const int*   ety   = (const int*)d_in[3];
    const float* W0    = (const float*)d_in[4];
    const float* loop0 = (const float*)d_in[5];
    const float* b0    = (const float*)d_in[6];
    const float* g0    = (const float*)d_in[7];
    const float* be0   = (const float*)d_in[8];
    const float* Ws    = (const float*)d_in[9];
    const float* loops = (const float*)d_in[10];
    const float* bs    = (const float*)d_in[11];
    const float* gs    = (const float*)d_in[12];
    const float* bes   = (const float*)d_in[13];
    const float* Wl    = (const float*)d_in[14];
    const float* bl    = (const float*)d_in[15];
    const float* gl    = (const float*)d_in[16];
    const float* bel   = (const float*)d_in[17];

    int N = in_sizes[0] / 64;
    int E = in_sizes[1];
    float* out = (float*)d_out;
    float invN = 1.0f / (float)N;

    float* preP;
    __nv_bfloat16 *shiP, *sloP, *hhiP, *hloP, *wimgP;
    cudaGetSymbolAddress((void**)&preP, g_pre);
    cudaGetSymbolAddress((void**)&shiP, g_shi);
    cudaGetSymbolAddress((void**)&sloP, g_slo);
    cudaGetSymbolAddress((void**)&hhiP, g_hhi);
    cudaGetSymbolAddress((void**)&hloP, g_hlo);
    cudaGetSymbolAddress((void**)&wimgP, g_wimg);

    cudaFuncSetAttribute(k_gemm_mma, cudaFuncAttributeMaxDynamicSharedMemorySize, GEMM_SMEM);

    int tb = 256;
    int gE = (E + tb - 1) / tb;
    int gN = (N + tb - 1) / tb;
    int nb = (N + 255) / 256;
    int gW = (N * 32 + tb - 1) / tb;
    int gG = (N + 127) / 128;
    int gV = (N * 32 + tb - 1) / tb;

    // --- CSR build (by dst), parallel scan ---
    k_prep<<<gN, tb>>>(N);
    k_hist<<<gE, tb>>>(dst, E);
    k_scan1<<<nb, 256>>>(N);
    k_scan3<<<nb, 256>>>(N);
    k_fill<<<gE, tb>>>(src, dst, ety, E);

    // --- weight images (all layers, one launch) + x planes ---
    k_wimg<<<(54 * 2048 + tb - 1) / tb, tb>>>(W0, loop0, Ws, loops, Wl, 54 * 2048);
    k_splitx<<<(N * 16 + tb - 1) / tb, tb>>>(x, N * 16);

    // --- layer 0: K = 256 (agg) + 64 (x planes), stats slot 0 ---
    k_agg64<<<gW, tb>>>(x, N);
    k_gemm_mma<<<gG, tb, GEMM_SMEM>>>((const char*)shiP, (const char*)sloP, 256,
                                      (const char*)hhiP, (const char*)hloP, 64,
                                      (const char*)wimgP, b0, preP, N, 0);

    // --- hidden layers: K = 512 + 128, stats slots 1,2 (BN fused into agg) ---
    for (int l = 0; l < 2; l++) {
        const float* gm = (l == 0) ? g0 : gs + (l - 1) * 128;
        const float* bt = (l == 0) ? be0 : bes + (l - 1) * 128;
        k_agg128bn<<<gW, tb>>>(preP, gm, bt, l, invN, N);
        k_gemm_mma<<<gG, tb, GEMM_SMEM>>>((const char*)shiP, (const char*)sloP, 512,
                                          (const char*)hhiP, (const char*)hloP, 128,
                                          (const char*)wimgP + (size_t)(10 + l * 20) * 16384,
                                          bs + l * 128, preP, N, l + 1);
    }

    // --- final linear: K = 128 (h2 planes), stats slot 3 ---
    k_bn_post<<<gV, tb>>>(preP, gs + 128, bes + 128, (float*)nullptr, hhiP, hloP, 2, 1, invN, N);
    k_gemm_mma<<<gG, tb, GEMM_SMEM>>>((const char*)hhiP, (const char*)hloP, 128,
                                      (const char*)hhiP, (const char*)hloP, 0,
                                      (const char*)wimgP + (size_t)50 * 16384, bl, preP, N, 3);
    k_bn_post<<<gV, tb>>>(preP, gl, bel, out, (__nv_bfloat16*)nullptr, (__nv_bfloat16*)nullptr,
                          3, 0, invN, N);
}

// round 16
// speedup vs baseline: 1.1399x; 1.0783x over previous
#include <cuda_runtime.h>
#include <cuda_bf16.h>
#include <cstdint>

#define NMAX 100000
#define EMAX 1600000
#define EPS 1e-5f

// ------------------- device scratch (no allocations allowed) -------------------
__device__ __nv_bfloat16 g_shi[(size_t)NMAX * 512];   // aggregated features, hi plane
__device__ __nv_bfloat16 g_slo[(size_t)NMAX * 512];   // aggregated features, lo plane
__device__ __nv_bfloat16 g_hhi[(size_t)NMAX * 128];   // activation hi plane (also x planes)
__device__ __nv_bfloat16 g_hlo[(size_t)NMAX * 128];   // activation lo plane
__device__ float g_pre[(size_t)NMAX * 128];           // pre-BN buffer
__device__ __nv_bfloat16 g_wimg[(size_t)54 * 8192];   // pre-swizzled weight chunk images (16KB each)
__device__ int   g_rowptr[NMAX + 1];
__device__ int   g_cursor[NMAX];
__device__ int   g_edges[EMAX];                       // packed (src<<2)|etype, sorted by dst
__device__ int   g_bsum[512];                         // per-block count sums for scan
__device__ float g_sums[4 * 128];                     // BN stats slots (one per layer)
__device__ float g_sumsq[4 * 128];

// ------------------- helpers -------------------
__device__ __forceinline__ uint32_t smem_u32(const void* p) {
    uint32_t a;
    asm("{ .reg .u64 t; cvta.to.shared.u64 t, %1; cvt.u32.u64 %0, t; }" : "=r"(a) : "l"(p));
    return a;
}
#define SW64(x) ((x) ^ (((x) >> 3) & 0x30))

#define LDSM_X4(r, addr) \
    asm volatile("ldmatrix.sync.aligned.m8n8.x4.shared.b16 {%0,%1,%2,%3}, [%4];" \
        : "=r"((r)[0]), "=r"((r)[1]), "=r"((r)[2]), "=r"((r)[3]) : "r"(addr))

#define MMA_BF16(d, a, b0v, b1v) \
    asm volatile("mma.sync.aligned.m16n8k16.row.col.f32.bf16.bf16.f32 " \
        "{%0,%1,%2,%3}, {%4,%5,%6,%7}, {%8,%9}, {%0,%1,%2,%3};" \
        : "+f"((d)[0]), "+f"((d)[1]), "+f"((d)[2]), "+f"((d)[3]) \
        : "r"((a)[0]), "r"((a)[1]), "r"((a)[2]), "r"((a)[3]), "r"(b0v), "r"(b1v))

#define CP16(dst, src) \
    asm volatile("cp.async.cg.shared.global [%0], [%1], 16;" :: "r"(dst), "l"(src) : "memory")
#define CP_COMMIT() asm volatile("cp.async.commit_group;" ::: "memory")
#define CP_WAIT1()  asm volatile("cp.async.wait_group 1;" ::: "memory")
#define CP_WAIT0()  asm volatile("cp.async.wait_group 0;" ::: "memory")

// hi/lo bf16 split of a float pair: packed u32 (low half = x, high half = y)
__device__ __forceinline__ void split2(float x, float y, uint32_t& hi, uint32_t& lo) {
    uint32_t h;
    asm("cvt.rn.bf16x2.f32 %0, %1, %2;" : "=r"(h) : "f"(y), "f"(x));
    float hx = __uint_as_float(h << 16);
    float hy = __uint_as_float(h & 0xFFFF0000u);
    float lx = x - hx, ly = y - hy;
    uint32_t l;
    asm("cvt.rn.bf16x2.f32 %0, %1, %2;" : "=r"(l) : "f"(ly), "f"(lx));
    hi = h; lo = l;
}

// ------------------- CSR build -------------------
__global__ void k_prep(int n) {
    int i = blockIdx.x * blockDim.x + threadIdx.x;
    if (i < n) g_cursor[i] = 0;
    if (i < 512) { g_sums[i] = 0.f; g_sumsq[i] = 0.f; }
}

__global__ void k_hist(const int* __restrict__ dst, int E) {
    int i = blockIdx.x * blockDim.x + threadIdx.x;
    if (i < E) atomicAdd(&g_cursor[dst[i]], 1);
}

__global__ void k_scan1(int n) {
    __shared__ int sh[256];
    int i = blockIdx.x * 256 + threadIdx.x;
    sh[threadIdx.x] = (i < n) ? g_cursor[i] : 0;
    __syncthreads();
    for (int off = 128; off > 0; off >>= 1) {
        if (threadIdx.x < off) sh[threadIdx.x] += sh[threadIdx.x + off];
        __syncthreads();
    }
    if (threadIdx.x == 0) g_bsum[blockIdx.x] = sh[0];
}

__global__ void k_scan3(int n) {
    __shared__ int sh[256];
    __shared__ int sc[256];
    int b = blockIdx.x, tid = threadIdx.x;
    int i = b * 256 + tid;
    int cp = 0;
    for (int j = tid; j < b; j += 256) cp += g_bsum[j];
    sc[tid] = cp;
    int v = (i < n) ? g_cursor[i] : 0;
    sh[tid] = v;
    __syncthreads();
    for (int off = 128; off > 0; off >>= 1) {
        if (tid < off) sc[tid] += sc[tid + off];
        __syncthreads();
    }
    int carry = sc[0];
    for (int off = 1; off < 256; off <<= 1) {
        int t = (tid >= off) ? sh[tid - off] : 0;
        __syncthreads();
        sh[tid] += t;
        __syncthreads();
    }
    int incl = sh[tid];
    if (i < n) {
        g_rowptr[i + 1] = carry + incl;
        g_cursor[i] = carry + incl - v;
    }
    if (b == 0 && tid == 0) g_rowptr[0] = 0;
}

__global__ void k_fill(const int* __restrict__ src, const int* __restrict__ dst,
                       const int* __restrict__ ety, int E) {
    int i = blockIdx.x * blockDim.x + threadIdx.x;
    if (i < E) {
        int pos = atomicAdd(&g_cursor[dst[i]], 1);
        g_edges[pos] = (src[i] << 2) | ety[i];
    }
}

// ------------------- weight images (SW64, 32-k chunks, fused all layers) -------------------
__global__ void k_wimg(const float* __restrict__ W0, const float* __restrict__ loop0,
                       const float* __restrict__ Ws, const float* __restrict__ loops,
                       const float* __restrict__ Wl, int total) {
    int t = blockIdx.x * blockDim.x + threadIdx.x;
    if (t >= total) return;                 // total = 54 * 2048
    int g = t >> 11;
    int rem = t & 2047;
    int ncol = rem >> 4;                    // 0..127
    int kp = rem & 15;                      // k pair 0..15
    const float *W1, *W2; int K1, lc;
    if (g < 10)      { W1 = W0; W2 = loop0; K1 = 256; lc = g; }
    else if (g < 30) { W1 = Ws; W2 = loops; K1 = 512; lc = g - 10; }
    else if (g < 50) { W1 = Ws + (size_t)4 * 128 * 128; W2 = loops + (size_t)128 * 128; K1 = 512; lc = g - 30; }
    else             { W1 = Wl; W2 = Wl; K1 = 128; lc = g - 50; }
    int kg = lc * 32 + kp * 2;
    const float* Wsrc; int krow;
    if (kg < K1) { Wsrc = W1; krow = kg; } else { Wsrc = W2; krow = kg - K1; }
    float w0 = __ldg(Wsrc + (size_t)krow * 128 + ncol);
    float w1 = __ldg(Wsrc + (size_t)(krow + 1) * 128 + ncol);
    uint32_t h, l;
    split2(w0, w1, h, l);
    uint32_t off = SW64((uint32_t)(ncol * 64 + kp * 4));
    char* cb = (char*)g_wimg + (size_t)g * 16384;
    *(uint32_t*)(cb + off) = h;
    *(uint32_t*)(cb + 8192 + off) = l;
}

// ------------------- x split (one-shot) -------------------
__global__ void k_splitx(const float* __restrict__ x, int total4) {
    int idx = blockIdx.x * blockDim.x + threadIdx.x;
    if (idx >= total4) return;
    float4 v = ((const float4*)x)[idx];
    uint32_t h01, l01, h23, l23;
    split2(v.x, v.y, h01, l01);
    split2(v.z, v.w, h23, l23);
    ((uint2*)g_hhi)[idx] = make_uint2(h01, h23);
    ((uint2*)g_hlo)[idx] = make_uint2(l01, l23);
}

// ------------------- aggregation (one warp per node, no atomics) -------------------
// layer0: raw x (F=64), unroll 4 for MLP
__global__ void k_agg64(const float* __restrict__ x, int N) {
    int w = (blockIdx.x * blockDim.x + threadIdx.x) >> 5;
    if (w >= N) return;
    int lane = threadIdx.x & 31;
    int col = lane * 2;
    float2 a0 = make_float2(0.f, 0.f), a1 = a0, a2 = a0, a3 = a0;
    int e = g_rowptr[w], eend = g_rowptr[w + 1];
    for (; e + 4 <= eend; e += 4) {
        int pk0 = __ldg(&g_edges[e]);
        int pk1 = __ldg(&g_edges[e + 1]);
        int pk2 = __ldg(&g_edges[e + 2]);
        int pk3 = __ldg(&g_edges[e + 3]);
        float2 v0 = *(const float2*)(x + (size_t)(pk0 >> 2) * 64 + col);
        float2 v1 = *(const float2*)(x + (size_t)(pk1 >> 2) * 64 + col);
        float2 v2 = *(const float2*)(x + (size_t)(pk2 >> 2) * 64 + col);
        float2 v3 = *(const float2*)(x + (size_t)(pk3 >> 2) * 64 + col);
        int r;
        r = pk0 & 3;
        if (r == 0)      { a0.x += v0.x; a0.y += v0.y; }
        else if (r == 1) { a1.x += v0.x; a1.y += v0.y; }
        else if (r == 2) { a2.x += v0.x; a2.y += v0.y; }
        else             { a3.x += v0.x; a3.y += v0.y; }
        r = pk1 & 3;
        if (r == 0)      { a0.x += v1.x; a0.y += v1.y; }
        else if (r == 1) { a1.x += v1.x; a1.y += v1.y; }
        else if (r == 2) { a2.x += v1.x; a2.y += v1.y; }
        else             { a3.x += v1.x; a3.y += v1.y; }
        r = pk2 & 3;
        if (r == 0)      { a0.x += v2.x; a0.y += v2.y; }
        else if (r == 1) { a1.x += v2.x; a1.y += v2.y; }
        else if (r == 2) { a2.x += v2.x; a2.y += v2.y; }
        else             { a3.x += v2.x; a3.y += v2.y; }
        r = pk3 & 3;
        if (r == 0)      { a0.x += v3.x; a0.y += v3.y; }
        else if (r == 1) { a1.x += v3.x; a1.y += v3.y; }
        else if (r == 2) { a2.x += v3.x; a2.y += v3.y; }
        else             { a3.x += v3.x; a3.y += v3.y; }
    }
    for (; e < eend; ++e) {
        int pk = __ldg(&g_edges[e]);
        float2 v = *(const float2*)(x + (size_t)(pk >> 2) * 64 + col);
        int r = pk & 3;
        if (r == 0)      { a0.x += v.x; a0.y += v.y; }
        else if (r == 1) { a1.x += v.x; a1.y += v.y; }
        else if (r == 2) { a2.x += v.x; a2.y += v.y; }
        else             { a3.x += v.x; a3.y += v.y; }
    }
    size_t base = (size_t)w * 256 + col;
    float2 acc[4] = {a0, a1, a2, a3};
    #pragma unroll
    for (int r = 0; r < 4; ++r) {
        uint32_t h01, l01;
        split2(acc[r].x, acc[r].y, h01, l01);
        size_t bo = (base + r * 64) * 2;
        *(uint32_t*)((char*)g_shi + bo) = h01;
        *(uint32_t*)((char*)g_slo + bo) = l01;
    }
}

// hidden layers: gather from g_pre with BN+ReLU inline (F=128), unroll 4.
// Also writes the node's own BN'd activation planes (merged k_bn_post).
__global__ void k_agg128bn(const float* __restrict__ pre,
                           const float* __restrict__ gamma,
                           const float* __restrict__ beta,
                           int slot, float invN, int N) {
    int w = (blockIdx.x * blockDim.x + threadIdx.x) >> 5;
    if (w >= N) return;
    int lane = threadIdx.x & 31;
    int col = lane * 4;
    float mu[4], sc[4], be[4];
    #pragma unroll
    for (int j = 0; j < 4; ++j) {
        int c = col + j;
        float s = g_sums[slot * 128 + c], q = g_sumsq[slot * 128 + c];
        float m = s * invN;
        float var = q * invN - m * m;
        mu[j] = m;
        sc[j] = __ldg(gamma + c) * rsqrtf(var + EPS);
        be[j] = __ldg(beta + c);
    }

    // self row: BN+ReLU+split -> activation planes (merged bn_post)
    {
        float4 v = *(const float4*)(pre + (size_t)w * 128 + col);
        float y0 = fmaxf((v.x - mu[0]) * sc[0] + be[0], 0.f);
        float y1 = fmaxf((v.y - mu[1]) * sc[1] + be[1], 0.f);
        float y2 = fmaxf((v.z - mu[2]) * sc[2] + be[2], 0.f);
        float y3 = fmaxf((v.w - mu[3]) * sc[3] + be[3], 0.f);
        uint32_t h01, l01, h23, l23;
        split2(y0, y1, h01, l01);
        split2(y2, y3, h23, l23);
        size_t ho = ((size_t)w * 128 + col) * 2;
        *(uint2*)((char*)g_hhi + ho) = make_uint2(h01, h23);
        *(uint2*)((char*)g_hlo + ho) = make_uint2(l01, l23);
    }

    float4 a0 = make_float4(0.f, 0.f, 0.f, 0.f), a1 = a0, a2 = a0, a3 = a0;
    int e = g_rowptr[w], eend = g_rowptr[w + 1];
    for (; e + 4 <= eend; e += 4) {
        int pk0 = __ldg(&g_edges[e]);
        int pk1 = __ldg(&g_edges[e + 1]);
        int pk2 = __ldg(&g_edges[e + 2]);
        int pk3 = __ldg(&g_edges[e + 3]);
        float4 v0 = *(const float4*)(pre + (size_t)(pk0 >> 2) * 128 + col);
        float4 v1 = *(const float4*)(pre + (size_t)(pk1 >> 2) * 128 + col);
        float4 v2 = *(const float4*)(pre + (size_t)(pk2 >> 2) * 128 + col);
        float4 v3 = *(const float4*)(pre + (size_t)(pk3 >> 2) * 128 + col);
        #pragma unroll
        for (int u = 0; u < 4; ++u) {
            float4 v = (u == 0) ? v0 : (u == 1) ? v1 : (u == 2) ? v2 : v3;
            int pk = (u == 0) ? pk0 : (u == 1) ? pk1 : (u == 2) ? pk2 : pk3;
            v.x = fmaxf((v.x - mu[0]) * sc[0] + be[0], 0.f);
            v.y = fmaxf((v.y - mu[1]) * sc[1] + be[1], 0.f);
            v.z = fmaxf((v.z - mu[2]) * sc[2] + be[2], 0.f);
            v.w = fmaxf((v.w - mu[3]) * sc[3] + be[3], 0.f);
            int r = pk & 3;
            if (r == 0)      { a0.x += v.x; a0.y += v.y; a0.z += v.z; a0.w += v.w; }
            else if (r == 1) { a1.x += v.x; a1.y += v.y; a1.z += v.z; a1.w += v.w; }
            else if (r == 2) { a2.x += v.x; a2.y += v.y; a2.z += v.z; a2.w += v.w; }
            else             { a3.x += v.x; a3.y += v.y; a3.z += v.z; a3.w += v.w; }
        }
    }
    for (; e < eend; ++e) {
        int pk = __ldg(&g_edges[e]);
        float4 v = *(const float4*)(pre + (size_t)(pk >> 2) * 128 + col);
        v.x = fmaxf((v.x - mu[0]) * sc[0] + be[0], 0.f);
        v.y = fmaxf((v.y - mu[1]) * sc[1] + be[1], 0.f);
        v.z = fmaxf((v.z - mu[2]) * sc[2] + be[2], 0.f);
        v.w = fmaxf((v.w - mu[3]) * sc[3] + be[3], 0.f);
        int r = pk & 3;
        if (r == 0)      { a0.x += v.x; a0.y += v.y; a0.z += v.z; a0.w += v.w; }
        else if (r == 1) { a1.x += v.x; a1.y += v.y; a1.z += v.z; a1.w += v.w; }
        else if (r == 2) { a2.x += v.x; a2.y += v.y; a2.z += v.z; a2.w += v.w; }
        else             { a3.x += v.x; a3.y += v.y; a3.z += v.z; a3.w += v.w; }
    }
    size_t base = (size_t)w * 512 + col;
    float4 acc[4] = {a0, a1, a2, a3};
    #pragma unroll
    for (int r = 0; r < 4; ++r) {
        uint32_t h01, l01, h23, l23;
        split2(acc[r].x, acc[r].y, h01, l01);
        split2(acc[r].z, acc[r].w, h23, l23);
        size_t bo = (base + r * 128) * 2;
        *(uint2*)((char*)g_shi + bo) = make_uint2(h01, h23);
        *(uint2*)((char*)g_slo + bo) = make_uint2(l01, l23);
    }
}

// ------------------- bf16-split GEMM, cp.async 2-stage pipeline -------------------
// Fragment-reuse inner loop: per k-step load Ah+Bh (MMA), Bl (MMA, reuse Ah),
// Al+Bh (MMA) -> 28 LDSM/chunk vs 36.
#define GEMM_SMEM 65536

__global__ void __launch_bounds__(256, 2)
k_gemm_mma(const char* __restrict__ A1h, const char* __restrict__ A1l, int K1,
           const char* __restrict__ A2h, const char* __restrict__ A2l, int K2,
           const char* __restrict__ wimg,
           const float* __restrict__ bias,
           float* __restrict__ C, int n, int slot) {
    extern __shared__ char smem[];
    uint32_t sb = smem_u32(smem);
    int tid = threadIdx.x;
    int lane = tid & 31;
    int wid = tid >> 5;
    int wm = (wid & 1) * 64;
    int wn = (wid >> 1) * 32;
    int m0 = blockIdx.x * 128;
    int K = K1 + K2;
    int NC = K >> 5;

    uint32_t xorv = (uint32_t)(lane & 6) << 3;
    uint32_t colA = (uint32_t)(lane >> 4) * 16;
    uint32_t colB = (uint32_t)((lane >> 3) & 1) * 16;
    uint32_t rbA[4], rbB[2];
    #pragma unroll
    for (int i = 0; i < 4; ++i)
        rbA[i] = (uint32_t)(wm + (lane & 15) + i * 16) * 64;
    #pragma unroll
    for (int j = 0; j < 2; ++j)
        rbB[j] = (uint32_t)(wn + j * 16 + ((lane >> 4) << 3) + (lane & 7)) * 64;

    float acc[4][4][4];
    #pragma unroll
    for (int i = 0; i < 4; ++i)
        #pragma unroll
        for (int f = 0; f < 4; ++f)
            #pragma unroll
            for (int q = 0; q < 4; ++q) acc[i][f][q] = 0.f;

    auto stage = [&](int c, int buf) {
        int ck0 = c * 32;
        const char *ph, *pl; size_t rst, rofs;
        if (ck0 < K1) { ph = A1h; pl = A1l; rst = (size_t)K1 * 2; rofs = (size_t)ck0 * 2; }
        else          { ph = A2h; pl = A2l; rst = (size_t)K2 * 2; rofs = (size_t)(ck0 - K1) * 2; }
        uint32_t base = sb + buf * 32768;
        #pragma unroll
        for (int i = 0; i < 2; ++i) {
            int idx = i * 256 + tid;          // 0..511
            int row = idx >> 2;
            int seg = idx & 3;
            int grow = m0 + row; if (grow >= n) grow = n - 1;
            size_t so = (size_t)grow * rst + rofs + seg * 16;
            uint32_t d = base + SW64((uint32_t)(row * 64 + seg * 16));
            CP16(d, ph + so);
            CP16(d + 8192, pl + so);
        }
        const char* img = wimg + (size_t)c * 16384;
        #pragma unroll
        for (int i = 0; i < 2; ++i) {
            int idx = i * 256 + tid;
            CP16(base + 16384 + idx * 16, img + idx * 16);
            CP16(base + 24576 + idx * 16, img + 8192 + idx * 16);
        }
    };

    stage(0, 0);
    CP_COMMIT();
    for (int c = 0; c < NC; ++c) {
        if (c + 1 < NC) {
            stage(c + 1, (c + 1) & 1);
            CP_COMMIT();
            CP_WAIT1();
        } else {
            CP_WAIT0();
        }
        __syncthreads();
        uint32_t base = sb + (c & 1) * 32768;
        uint32_t Ah = base, Al = base + 8192, Bh = base + 16384, Bl = base + 24576;
        #pragma unroll
        for (int kk = 0; kk < 2; ++kk) {
            uint32_t cA = (colA + (uint32_t)kk * 32) ^ xorv;
            uint32_t cB = (colB + (uint32_t)kk * 32) ^ xorv;
            uint32_t a[4][4], b[2][4];
            // pass 1: Ah * Bh
            #pragma unroll
            for (int i = 0; i < 4; ++i) LDSM_X4(a[i], Ah + rbA[i] + cA);
            #pragma unroll
            for (int j = 0; j < 2; ++j) LDSM_X4(b[j], Bh + rbB[j] + cB);
            #pragma unroll
            for (int i = 0; i < 4; ++i) {
                MMA_BF16(acc[i][0], a[i], b[0][0], b[0][1]);
                MMA_BF16(acc[i][1], a[i], b[0][2], b[0][3]);
                MMA_BF16(acc[i][2], a[i], b[1][0], b[1][1]);
                MMA_BF16(acc[i][3], a[i], b[1][2], b[1][3]);
            }
            // pass 2: Ah * Bl (reuse a)
            #pragma unroll
            for (int j = 0; j < 2; ++j) LDSM_X4(b[j], Bl + rbB[j] + cB);
            #pragma unroll
            for (int i = 0; i < 4; ++i) {
                MMA_BF16(acc[i][0], a[i], b[0][0], b[0][1]);
                MMA_BF16(acc[i][1], a[i], b[0][2], b[0][3]);
                MMA_BF16(acc[i][2], a[i], b[1][0], b[1][1]);
                MMA_BF16(acc[i][3], a[i], b[1][2], b[1][3]);
            }
            // pass 3: Al * Bh
            #pragma unroll
            for (int i = 0; i < 4; ++i) LDSM_X4(a[i], Al + rbA[i] + cA);
            #pragma unroll
            for (int j = 0; j < 2; ++j) LDSM_X4(b[j], Bh + rbB[j] + cB);
            #pragma unroll
            for (int i = 0; i < 4; ++i) {
                MMA_BF16(acc[i][0], a[i], b[0][0], b[0][1]);
                MMA_BF16(acc[i][1], a[i], b[0][2], b[0][3]);
                MMA_BF16(acc[i][2], a[i], b[1][0], b[1][1]);
                MMA_BF16(acc[i][3], a[i], b[1][2], b[1][3]);
            }
        }
        __syncthreads();
    }

    // ---- epilogue: bias add + store + fused BN stats ----
    float* s_sum = (float*)smem;     // [128]
    float* s_sq  = s_sum + 128;      // [128]
    if (tid < 128) { s_sum[tid] = 0.f; s_sq[tid] = 0.f; }
    __syncthreads();

    int g = lane >> 2, t = lane & 3;
    #pragma unroll
    for (int f = 0; f < 4; ++f) {
        int col = wn + f * 8 + t * 2;
        float bx = __ldg(bias + col), by = __ldg(bias + col + 1);
        float ls0 = 0.f, lq0 = 0.f, ls1 = 0.f, lq1 = 0.f;
        #pragma unroll
        for (int i = 0; i < 4; ++i) {
            int r0 = m0 + wm + i * 16 + g;
            if (r0 < n) {
                float y0 = acc[i][f][0] + bx, y1 = acc[i][f][1] + by;
                *(float2*)(C + (size_t)r0 * 128 + col) = make_float2(y0, y1);
                ls0 += y0; lq0 += y0 * y0; ls1 += y1; lq1 += y1 * y1;
            }
            int r1 = r0 + 8;
            if (r1 < n) {
                float y0 = acc[i][f][2] + bx, y1 = acc[i][f][3] + by;
                *(float2*)(C + (size_t)r1 * 128 + col) = make_float2(y0, y1);
                ls0 += y0; lq0 += y0 * y0; ls1 += y1; lq1 += y1 * y1;
            }
        }
        atomicAdd(&s_sum[col], ls0); atomicAdd(&s_sq[col], lq0);
        atomicAdd(&s_sum[col + 1], ls1); atomicAdd(&s_sq[col + 1], lq1);
    }
    __syncthreads();
    if (tid < 128) {
        atomicAdd(&g_sums[slot * 128 + tid], s_sum[tid]);
        atomicAdd(&g_sumsq[slot * 128 + tid], s_sq[tid]);
    }
}

// ------------------- BN post: planes and/or fp32 out -------------------
__global__ void k_bn_post(const float* __restrict__ pre,
                          const float* __restrict__ gamma,
                          const float* __restrict__ beta,
                          float* __restrict__ out,
                          __nv_bfloat16* __restrict__ phi,
                          __nv_bfloat16* __restrict__ plo,
                          int slot, int relu, float invN, int n) {
    int idx = blockIdx.x * blockDim.x + threadIdx.x;
    if (idx >= n * 32) return;
    int c4 = (idx & 31) * 4;
    float4 v = ((const float4*)pre)[idx];
    float y[4];
    #pragma unroll
    for (int j = 0; j < 4; j++) {
        int c = c4 + j;
        float mu = g_sums[slot * 128 + c] * invN;
        float var = g_sumsq[slot * 128 + c] * invN - mu * mu;
        float sc = __ldg(gamma + c) * rsqrtf(var + EPS);
        float be = __ldg(beta + c);
        float x = (j == 0) ? v.x : (j == 1) ? v.y : (j == 2) ? v.z : v.w;
        float yy = (x - mu) * sc + be;
        if (relu) yy = fmaxf(yy, 0.f);
        y[j] = yy;
    }
    if (out) ((float4*)out)[idx] = make_float4(y[0], y[1], y[2], y[3]);
    if (phi) {
        uint32_t h01, l01, h23, l23;
        split2(y[0], y[1], h01, l01);
        split2(y[2], y[3], h23, l23);
        ((uint2*)phi)[idx] = make_uint2(h01, h23);
        ((uint2*)plo)[idx] = make_uint2(l01, l23);
    }
}

// ------------------- launcher -------------------
extern "C" void kernel_launch(void* const* d_in, const int* in_sizes, int n_in,
                              void* d_out, int out_size) {
    const float* x     = (const float*)d_in[0];
    const int*   src   = (const int*)d_in[1];
    const int*   dst   = (const int*)d_in[2];
    const int*   ety   = (const int*)d_in[3];
    const float* W0    = (const float*)d_in[4];
    const float* loop0 = (const float*)d_in[5];
    const float* b0    = (const float*)d_in[6];
    const float* g0    = (const float*)d_in[7];
    const float* be0   = (const float*)d_in[8];
    const float* Ws    = (const float*)d_in[9];
    const float* loops = (const float*)d_in[10];
    const float* bs    = (const float*)d_in[11];
    const float* gs    = (const float*)d_in[12];
    const float* bes   = (const float*)d_in[13];
    const float* Wl    = (const float*)d_in[14];
    const float* bl    = (const float*)d_in[15];
    const float* gl    = (const float*)d_in[16];
    const float* bel   = (const float*)d_in[17];

    int N = in_sizes[0] / 64;
    int E = in_sizes[1];
    float* out = (float*)d_out;
    float invN = 1.0f / (float)N;

    float* preP;
    __nv_bfloat16 *shiP, *sloP, *hhiP, *hloP, *wimgP;
    cudaGetSymbolAddress((void**)&preP, g_pre);
    cudaGetSymbolAddress((void**)&shiP, g_shi);
    cudaGetSymbolAddress((void**)&sloP, g_slo);
    cudaGetSymbolAddress((void**)&hhiP, g_hhi);
    cudaGetSymbolAddress((void**)&hloP, g_hlo);
    cudaGetSymbolAddress((void**)&wimgP, g_wimg);

    cudaFuncSetAttribute(k_gemm_mma, cudaFuncAttributeMaxDynamicSharedMemorySize, GEMM_SMEM);

    int tb = 256;
    int gE = (E + tb - 1) / tb;
    int gN = (N + tb - 1) / tb;
    int nb = (N + 255) / 256;
    int gW = (N * 32 + tb - 1) / tb;
    int gG = (N + 127) / 128;
    int gV = (N * 32 + tb - 1) / tb;

    // --- CSR build (by dst), parallel scan ---
    k_prep<<<gN, tb>>>(N);
    k_hist<<<gE, tb>>>(dst, E);
    k_scan1<<<nb, 256>>>(N);
    k_scan3<<<nb, 256>>>(N);
    k_fill<<<gE, tb>>>(src, dst, ety, E);

    // --- weight images (all layers, one launch) + x planes ---
    k_wimg<<<(54 * 2048 + tb - 1) / tb, tb>>>(W0, loop0, Ws, loops, Wl, 54 * 2048);
    k_splitx<<<(N * 16 + tb - 1) / tb, tb>>>(x, N * 16);

    // --- layer 0: K = 256 (agg) + 64 (x planes), stats slot 0 ---
    k_agg64<<<gW, tb>>>(x, N);
    k_gemm_mma<<<gG, tb, GEMM_SMEM>>>((const char*)shiP, (const char*)sloP, 256,
                                      (const char*)hhiP, (const char*)hloP, 64,
                                      (const char*)wimgP, b0, preP, N, 0);

    // --- hidden layers: K = 512 + 128, stats slots 1,2 (BN fused into agg) ---
    for (int l = 0; l < 2; l++) {
        const float* gm = (l == 0) ? g0 : gs + (l - 1) * 128;
        const float* bt = (l == 0) ? be0 : bes + (l - 1) * 128;
        k_agg128bn<<<gW, tb>>>(preP, gm, bt, l, invN, N);
        k_gemm_mma<<<gG, tb, GEMM_SMEM>>>((const char*)shiP, (const char*)sloP, 512,
                                          (const char*)hhiP, (const char*)hloP, 128,
                                          (const char*)wimgP + (size_t)(10 + l * 20) * 16384,
                                          bs + l * 128, preP, N, l + 1);
    }

    // --- final linear: K = 128 (h2 planes), stats slot 3 ---
    k_bn_post<<<gV, tb>>>(preP, gs + 128, bes + 128, (float*)nullptr, hhiP, hloP, 2, 1, invN, N);
    k_gemm_mma<<<gG, tb, GEMM_SMEM>>>((const char*)hhiP, (const char*)hloP, 128,
                                      (const char*)hhiP, (const char*)hloP, 0,
                                      (const char*)wimgP + (size_t)50 * 16384, bl, preP, N, 3);
    k_bn_post<<<gV, tb>>>(preP, gl, bel, out, (__nv_bfloat16*)nullptr, (__nv_bfloat16*)nullptr,
                          3, 0, invN, N);
}

// round 17
// speedup vs baseline: 1.1489x; 1.0079x over previous
#include <cuda_runtime.h>
#include <cuda_bf16.h>
#include <cstdint>

#define NMAX 100000
#define EMAX 1600000
#define EPS 1e-5f

// ------------------- device scratch (no allocations allowed) -------------------
__device__ __nv_bfloat16 g_shi[(size_t)NMAX * 512];   // aggregated features, hi plane
__device__ __nv_bfloat16 g_slo[(size_t)NMAX * 512];   // aggregated features, lo plane
__device__ __nv_bfloat16 g_hhi[(size_t)NMAX * 128];   // activation hi plane (also x planes)
__device__ __nv_bfloat16 g_hlo[(size_t)NMAX * 128];   // activation lo plane
__device__ float g_pre[(size_t)NMAX * 128];           // pre-BN buffer
__device__ __nv_bfloat16 g_wimg[(size_t)54 * 8192];   // pre-swizzled weight chunk images (16KB each)
__device__ int   g_rowptr[NMAX + 1];
__device__ int   g_cursor[NMAX];
__device__ int   g_edges[EMAX];                       // packed (src<<2)|etype, sorted by dst
__device__ int   g_bsum[512];                         // per-block count sums for scan
__device__ float g_sums[4 * 128];                     // BN stats slots (one per layer)
__device__ float g_sumsq[4 * 128];

// ------------------- helpers -------------------
__device__ __forceinline__ uint32_t smem_u32(const void* p) {
    uint32_t a;
    asm("{ .reg .u64 t; cvta.to.shared.u64 t, %1; cvt.u32.u64 %0, t; }" : "=r"(a) : "l"(p));
    return a;
}
#define SW64(x) ((x) ^ (((x) >> 3) & 0x30))

#define LDSM_X4(r, addr) \
    asm volatile("ldmatrix.sync.aligned.m8n8.x4.shared.b16 {%0,%1,%2,%3}, [%4];" \
        : "=r"((r)[0]), "=r"((r)[1]), "=r"((r)[2]), "=r"((r)[3]) : "r"(addr))

#define MMA_BF16(d, a, b0v, b1v) \
    asm volatile("mma.sync.aligned.m16n8k16.row.col.f32.bf16.bf16.f32 " \
        "{%0,%1,%2,%3}, {%4,%5,%6,%7}, {%8,%9}, {%0,%1,%2,%3};" \
        : "+f"((d)[0]), "+f"((d)[1]), "+f"((d)[2]), "+f"((d)[3]) \
        : "r"((a)[0]), "r"((a)[1]), "r"((a)[2]), "r"((a)[3]), "r"(b0v), "r"(b1v))

#define CP16(dst, src) \
    asm volatile("cp.async.cg.shared.global [%0], [%1], 16;" :: "r"(dst), "l"(src) : "memory")
#define CP_COMMIT() asm volatile("cp.async.commit_group;" ::: "memory")
#define CP_WAIT1()  asm volatile("cp.async.wait_group 1;" ::: "memory")
#define CP_WAIT0()  asm volatile("cp.async.wait_group 0;" ::: "memory")

// hi/lo bf16 split of a float pair: packed u32 (low half = x, high half = y)
__device__ __forceinline__ void split2(float x, float y, uint32_t& hi, uint32_t& lo) {
    uint32_t h;
    asm("cvt.rn.bf16x2.f32 %0, %1, %2;" : "=r"(h) : "f"(y), "f"(x));
    float hx = __uint_as_float(h << 16);
    float hy = __uint_as_float(h & 0xFFFF0000u);
    float lx = x - hx, ly = y - hy;
    uint32_t l;
    asm("cvt.rn.bf16x2.f32 %0, %1, %2;" : "=r"(l) : "f"(ly), "f"(lx));
    hi = h; lo = l;
}

// ------------------- CSR build -------------------
__global__ void k_hist(const int* __restrict__ dst, int E) {
    int i = blockIdx.x * blockDim.x + threadIdx.x;
    if (i < E) atomicAdd(&g_cursor[dst[i]], 1);
}

__global__ void k_scan1(int n) {
    __shared__ int sh[256];
    int i = blockIdx.x * 256 + threadIdx.x;
    sh[threadIdx.x] = (i < n) ? g_cursor[i] : 0;
    __syncthreads();
    for (int off = 128; off > 0; off >>= 1) {
        if (threadIdx.x < off) sh[threadIdx.x] += sh[threadIdx.x + off];
        __syncthreads();
    }
    if (threadIdx.x == 0) g_bsum[blockIdx.x] = sh[0];
}

__global__ void k_scan3(int n) {
    __shared__ int sh[256];
    __shared__ int sc[256];
    int b = blockIdx.x, tid = threadIdx.x;
    int i = b * 256 + tid;
    int cp = 0;
    for (int j = tid; j < b; j += 256) cp += g_bsum[j];
    sc[tid] = cp;
    int v = (i < n) ? g_cursor[i] : 0;
    sh[tid] = v;
    __syncthreads();
    for (int off = 128; off > 0; off >>= 1) {
        if (tid < off) sc[tid] += sc[tid + off];
        __syncthreads();
    }
    int carry = sc[0];
    for (int off = 1; off < 256; off <<= 1) {
        int t = (tid >= off) ? sh[tid - off] : 0;
        __syncthreads();
        sh[tid] += t;
        __syncthreads();
    }
    int incl = sh[tid];
    if (i < n) {
        g_rowptr[i + 1] = carry + incl;
        g_cursor[i] = carry + incl - v;
    }
    if (b == 0 && tid == 0) g_rowptr[0] = 0;
}

__global__ void k_fill(const int* __restrict__ src, const int* __restrict__ dst,
                       const int* __restrict__ ety, int E) {
    int i = blockIdx.x * blockDim.x + threadIdx.x;
    if (i < E) {
        int pos = atomicAdd(&g_cursor[dst[i]], 1);
        g_edges[pos] = (src[i] << 2) | ety[i];
    }
}

// ------------------- fused preprocessing: cursor/stats zero + weight images + x split -------------------
// block ranges: [0, nbP) prep, [nbP, nbP+nbW) wimg, [nbP+nbW, ...) splitx
__global__ void k_pre_all(const float* __restrict__ x,
                          const float* __restrict__ W0, const float* __restrict__ loop0,
                          const float* __restrict__ Ws, const float* __restrict__ loops,
                          const float* __restrict__ Wl,
                          int N, int nbP, int nbW) {
    int b = blockIdx.x;
    if (b < nbP) {
        int i = b * 256 + threadIdx.x;
        if (i < N) g_cursor[i] = 0;
        if (i < 512) { g_sums[i] = 0.f; g_sumsq[i] = 0.f; }
    } else if (b < nbP + nbW) {
        int t = (b - nbP) * 256 + threadIdx.x;
        if (t < 54 * 2048) {
            int g = t >> 11;
            int rem = t & 2047;
            int ncol = rem >> 4;
            int kp = rem & 15;
            const float *W1, *W2; int K1, lc;
            if (g < 10)      { W1 = W0; W2 = loop0; K1 = 256; lc = g; }
            else if (g < 30) { W1 = Ws; W2 = loops; K1 = 512; lc = g - 10; }
            else if (g < 50) { W1 = Ws + (size_t)4 * 128 * 128; W2 = loops + (size_t)128 * 128; K1 = 512; lc = g - 30; }
            else             { W1 = Wl; W2 = Wl; K1 = 128; lc = g - 50; }
            int kg = lc * 32 + kp * 2;
            const float* Wsrc; int krow;
            if (kg < K1) { Wsrc = W1; krow = kg; } else { Wsrc = W2; krow = kg - K1; }
            float w0 = __ldg(Wsrc + (size_t)krow * 128 + ncol);
            float w1 = __ldg(Wsrc + (size_t)(krow + 1) * 128 + ncol);
            uint32_t h, l;
            split2(w0, w1, h, l);
            uint32_t off = SW64((uint32_t)(ncol * 64 + kp * 4));
            char* cb = (char*)g_wimg + (size_t)g * 16384;
            *(uint32_t*)(cb + off) = h;
            *(uint32_t*)(cb + 8192 + off) = l;
        }
    } else {
        int idx = (b - nbP - nbW) * 256 + threadIdx.x;
        if (idx < N * 16) {
            float4 v = ((const float4*)x)[idx];
            uint32_t h01, l01, h23, l23;
            split2(v.x, v.y, h01, l01);
            split2(v.z, v.w, h23, l23);
            ((uint2*)g_hhi)[idx] = make_uint2(h01, h23);
            ((uint2*)g_hlo)[idx] = make_uint2(l01, l23);
        }
    }
}

// ------------------- aggregation (one warp per node, no atomics) -------------------
// layer0: raw x (F=64), unroll 4 for MLP
__global__ void k_agg64(const float* __restrict__ x, int N) {
    int w = (blockIdx.x * blockDim.x + threadIdx.x) >> 5;
    if (w >= N) return;
    int lane = threadIdx.x & 31;
    int col = lane * 2;
    float2 a0 = make_float2(0.f, 0.f), a1 = a0, a2 = a0, a3 = a0;
    int e = g_rowptr[w], eend = g_rowptr[w + 1];
    for (; e + 4 <= eend; e += 4) {
        int pk0 = __ldg(&g_edges[e]);
        int pk1 = __ldg(&g_edges[e + 1]);
        int pk2 = __ldg(&g_edges[e + 2]);
        int pk3 = __ldg(&g_edges[e + 3]);
        float2 v0 = *(const float2*)(x + (size_t)(pk0 >> 2) * 64 + col);
        float2 v1 = *(const float2*)(x + (size_t)(pk1 >> 2) * 64 + col);
        float2 v2 = *(const float2*)(x + (size_t)(pk2 >> 2) * 64 + col);
        float2 v3 = *(const float2*)(x + (size_t)(pk3 >> 2) * 64 + col);
        int r;
        r = pk0 & 3;
        if (r == 0)      { a0.x += v0.x; a0.y += v0.y; }
        else if (r == 1) { a1.x += v0.x; a1.y += v0.y; }
        else if (r == 2) { a2.x += v0.x; a2.y += v0.y; }
        else             { a3.x += v0.x; a3.y += v0.y; }
        r = pk1 & 3;
        if (r == 0)      { a0.x += v1.x; a0.y += v1.y; }
        else if (r == 1) { a1.x += v1.x; a1.y += v1.y; }
        else if (r == 2) { a2.x += v1.x; a2.y += v1.y; }
        else             { a3.x += v1.x; a3.y += v1.y; }
        r = pk2 & 3;
        if (r == 0)      { a0.x += v2.x; a0.y += v2.y; }
        else if (r == 1) { a1.x += v2.x; a1.y += v2.y; }
        else if (r == 2) { a2.x += v2.x; a2.y += v2.y; }
        else             { a3.x += v2.x; a3.y += v2.y; }
        r = pk3 & 3;
        if (r == 0)      { a0.x += v3.x; a0.y += v3.y; }
        else if (r == 1) { a1.x += v3.x; a1.y += v3.y; }
        else if (r == 2) { a2.x += v3.x; a2.y += v3.y; }
        else             { a3.x += v3.x; a3.y += v3.y; }
    }
    for (; e < eend; ++e) {
        int pk = __ldg(&g_edges[e]);
        float2 v = *(const float2*)(x + (size_t)(pk >> 2) * 64 + col);
        int r = pk & 3;
        if (r == 0)      { a0.x += v.x; a0.y += v.y; }
        else if (r == 1) { a1.x += v.x; a1.y += v.y; }
        else if (r == 2) { a2.x += v.x; a2.y += v.y; }
        else             { a3.x += v.x; a3.y += v.y; }
    }
    size_t base = (size_t)w * 256 + col;
    float2 acc[4] = {a0, a1, a2, a3};
    #pragma unroll
    for (int r = 0; r < 4; ++r) {
        uint32_t h01, l01;
        split2(acc[r].x, acc[r].y, h01, l01);
        size_t bo = (base + r * 64) * 2;
        *(uint32_t*)((char*)g_shi + bo) = h01;
        *(uint32_t*)((char*)g_slo + bo) = l01;
    }
}

// hidden layers: gather from g_pre with BN+ReLU inline (F=128), unroll 4.
// Also writes the node's own BN'd activation planes (merged k_bn_post).
__global__ void k_agg128bn(const float* __restrict__ pre,
                           const float* __restrict__ gamma,
                           const float* __restrict__ beta,
                           int slot, float invN, int N) {
    int w = (blockIdx.x * blockDim.x + threadIdx.x) >> 5;
    if (w >= N) return;
    int lane = threadIdx.x & 31;
    int col = lane * 4;
    float mu[4], sc[4], be[4];
    #pragma unroll
    for (int j = 0; j < 4; ++j) {
        int c = col + j;
        float s = g_sums[slot * 128 + c], q = g_sumsq[slot * 128 + c];
        float m = s * invN;
        float var = q * invN - m * m;
        mu[j] = m;
        sc[j] = __ldg(gamma + c) * rsqrtf(var + EPS);
        be[j] = __ldg(beta + c);
    }

    // self row: BN+ReLU+split -> activation planes (merged bn_post)
    {
        float4 v = *(const float4*)(pre + (size_t)w * 128 + col);
        float y0 = fmaxf((v.x - mu[0]) * sc[0] + be[0], 0.f);
        float y1 = fmaxf((v.y - mu[1]) * sc[1] + be[1], 0.f);
        float y2 = fmaxf((v.z - mu[2]) * sc[2] + be[2], 0.f);
        float y3 = fmaxf((v.w - mu[3]) * sc[3] + be[3], 0.f);
        uint32_t h01, l01, h23, l23;
        split2(y0, y1, h01, l01);
        split2(y2, y3, h23, l23);
        size_t ho = ((size_t)w * 128 + col) * 2;
        *(uint2*)((char*)g_hhi + ho) = make_uint2(h01, h23);
        *(uint2*)((char*)g_hlo + ho) = make_uint2(l01, l23);
    }

    float4 a0 = make_float4(0.f, 0.f, 0.f, 0.f), a1 = a0, a2 = a0, a3 = a0;
    int e = g_rowptr[w], eend = g_rowptr[w + 1];
    for (; e + 4 <= eend; e += 4) {
        int pk0 = __ldg(&g_edges[e]);
        int pk1 = __ldg(&g_edges[e + 1]);
        int pk2 = __ldg(&g_edges[e + 2]);
        int pk3 = __ldg(&g_edges[e + 3]);
        float4 v0 = *(const float4*)(pre + (size_t)(pk0 >> 2) * 128 + col);
        float4 v1 = *(const float4*)(pre + (size_t)(pk1 >> 2) * 128 + col);
        float4 v2 = *(const float4*)(pre + (size_t)(pk2 >> 2) * 128 + col);
        float4 v3 = *(const float4*)(pre + (size_t)(pk3 >> 2) * 128 + col);
        #pragma unroll
        for (int u = 0; u < 4; ++u) {
            float4 v = (u == 0) ? v0 : (u == 1) ? v1 : (u == 2) ? v2 : v3;
            int pk = (u == 0) ? pk0 : (u == 1) ? pk1 : (u == 2) ? pk2 : pk3;
            v.x = fmaxf((v.x - mu[0]) * sc[0] + be[0], 0.f);
            v.y = fmaxf((v.y - mu[1]) * sc[1] + be[1], 0.f);
            v.z = fmaxf((v.z - mu[2]) * sc[2] + be[2], 0.f);
            v.w = fmaxf((v.w - mu[3]) * sc[3] + be[3], 0.f);
            int r = pk & 3;
            if (r == 0)      { a0.x += v.x; a0.y += v.y; a0.z += v.z; a0.w += v.w; }
            else if (r == 1) { a1.x += v.x; a1.y += v.y; a1.z += v.z; a1.w += v.w; }
            else if (r == 2) { a2.x += v.x; a2.y += v.y; a2.z += v.z; a2.w += v.w; }
            else             { a3.x += v.x; a3.y += v.y; a3.z += v.z; a3.w += v.w; }
        }
    }
    for (; e < eend; ++e) {
        int pk = __ldg(&g_edges[e]);
        float4 v = *(const float4*)(pre + (size_t)(pk >> 2) * 128 + col);
        v.x = fmaxf((v.x - mu[0]) * sc[0] + be[0], 0.f);
        v.y = fmaxf((v.y - mu[1]) * sc[1] + be[1], 0.f);
        v.z = fmaxf((v.z - mu[2]) * sc[2] + be[2], 0.f);
        v.w = fmaxf((v.w - mu[3]) * sc[3] + be[3], 0.f);
        int r = pk & 3;
        if (r == 0)      { a0.x += v.x; a0.y += v.y; a0.z += v.z; a0.w += v.w; }
        else if (r == 1) { a1.x += v.x; a1.y += v.y; a1.z += v.z; a1.w += v.w; }
        else if (r == 2) { a2.x += v.x; a2.y += v.y; a2.z += v.z; a2.w += v.w; }
        else             { a3.x += v.x; a3.y += v.y; a3.z += v.z; a3.w += v.w; }
    }
    size_t base = (size_t)w * 512 + col;
    float4 acc[4] = {a0, a1, a2, a3};
    #pragma unroll
    for (int r = 0; r < 4; ++r) {
        uint32_t h01, l01, h23, l23;
        split2(acc[r].x, acc[r].y, h01, l01);
        split2(acc[r].z, acc[r].w, h23, l23);
        size_t bo = (base + r * 128) * 2;
        *(uint2*)((char*)g_shi + bo) = make_uint2(h01, h23);
        *(uint2*)((char*)g_slo + bo) = make_uint2(l01, l23);
    }
}

// ------------------- bf16-split GEMM, cp.async 2-stage pipeline -------------------
// Fragment-reuse inner loop, 24 LDSM/chunk: per k-step load Ah+Bh (MMA),
// Bl->bb (MMA reuse Ah), Al->a (MMA reuse Bh in b).
#define GEMM_SMEM 65536

__global__ void __launch_bounds__(256, 2)
k_gemm_mma(const char* __restrict__ A1h, const char* __restrict__ A1l, int K1,
           const char* __restrict__ A2h, const char* __restrict__ A2l, int K2,
           const char* __restrict__ wimg,
           const float* __restrict__ bias,
           float* __restrict__ C, int n, int slot) {
    extern __shared__ char smem[];
    uint32_t sb = smem_u32(smem);
    int tid = threadIdx.x;
    int lane = tid & 31;
    int wid = tid >> 5;
    int wm = (wid & 1) * 64;
    int wn = (wid >> 1) * 32;
    int m0 = blockIdx.x * 128;
    int K = K1 + K2;
    int NC = K >> 5;

    uint32_t xorv = (uint32_t)(lane & 6) << 3;
    uint32_t colA = (uint32_t)(lane >> 4) * 16;
    uint32_t colB = (uint32_t)((lane >> 3) & 1) * 16;
    uint32_t rbA[4], rbB[2];
    #pragma unroll
    for (int i = 0; i < 4; ++i)
        rbA[i] = (uint32_t)(wm + (lane & 15) + i * 16) * 64;
    #pragma unroll
    for (int j = 0; j < 2; ++j)
        rbB[j] = (uint32_t)(wn + j * 16 + ((lane >> 4) << 3) + (lane & 7)) * 64;

    float acc[4][4][4];
    #pragma unroll
    for (int i = 0; i < 4; ++i)
        #pragma unroll
        for (int f = 0; f < 4; ++f)
            #pragma unroll
            for (int q = 0; q < 4; ++q) acc[i][f][q] = 0.f;

    auto stage = [&](int c, int buf) {
        int ck0 = c * 32;
        const char *ph, *pl; size_t rst, rofs;
        if (ck0 < K1) { ph = A1h; pl = A1l; rst = (size_t)K1 * 2; rofs = (size_t)ck0 * 2; }
        else          { ph = A2h; pl = A2l; rst = (size_t)K2 * 2; rofs = (size_t)(ck0 - K1) * 2; }
        uint32_t base = sb + buf * 32768;
        #pragma unroll
        for (int i = 0; i < 2; ++i) {
            int idx = i * 256 + tid;          // 0..511
            int row = idx >> 2;
            int seg = idx & 3;
            int grow = m0 + row; if (grow >= n) grow = n - 1;
            size_t so = (size_t)grow * rst + rofs + seg * 16;
            uint32_t d = base + SW64((uint32_t)(row * 64 + seg * 16));
            CP16(d, ph + so);
            CP16(d + 8192, pl + so);
        }
        const char* img = wimg + (size_t)c * 16384;
        #pragma unroll
        for (int i = 0; i < 2; ++i) {
            int idx = i * 256 + tid;
            CP16(base + 16384 + idx * 16, img + idx * 16);
            CP16(base + 24576 + idx * 16, img + 8192 + idx * 16);
        }
    };

    stage(0, 0);
    CP_COMMIT();
    for (int c = 0; c < NC; ++c) {
        if (c + 1 < NC) {
            stage(c + 1, (c + 1) & 1);
            CP_COMMIT();
            CP_WAIT1();
        } else {
            CP_WAIT0();
        }
        __syncthreads();
        uint32_t base = sb + (c & 1) * 32768;
        uint32_t Ah = base, Al = base + 8192, Bh = base + 16384, Bl = base + 24576;
        #pragma unroll
        for (int kk = 0; kk < 2; ++kk) {
            uint32_t cA = (colA + (uint32_t)kk * 32) ^ xorv;
            uint32_t cB = (colB + (uint32_t)kk * 32) ^ xorv;
            uint32_t a[4][4], b[2][4], bb[2][4];
            // pass 1: Ah * Bh
            #pragma unroll
            for (int i = 0; i < 4; ++i) LDSM_X4(a[i], Ah + rbA[i] + cA);
            #pragma unroll
            for (int j = 0; j < 2; ++j) LDSM_X4(b[j], Bh + rbB[j] + cB);
            #pragma unroll
            for (int i = 0; i < 4; ++i) {
                MMA_BF16(acc[i][0], a[i], b[0][0], b[0][1]);
                MMA_BF16(acc[i][1], a[i], b[0][2], b[0][3]);
                MMA_BF16(acc[i][2], a[i], b[1][0], b[1][1]);
                MMA_BF16(acc[i][3], a[i], b[1][2], b[1][3]);
            }
            // pass 2: Ah * Bl (reuse a, Bl into bb keeping Bh in b)
            #pragma unroll
            for (int j = 0; j < 2; ++j) LDSM_X4(bb[j], Bl + rbB[j] + cB);
            #pragma unroll
            for (int i = 0; i < 4; ++i) {
                MMA_BF16(acc[i][0], a[i], bb[0][0], bb[0][1]);
                MMA_BF16(acc[i][1], a[i], bb[0][2], bb[0][3]);
                MMA_BF16(acc[i][2], a[i], bb[1][0], bb[1][1]);
                MMA_BF16(acc[i][3], a[i], bb[1][2], bb[1][3]);
            }
            // pass 3: Al * Bh (reuse b)
            #pragma unroll
            for (int i = 0; i < 4; ++i) LDSM_X4(a[i], Al + rbA[i] + cA);
            #pragma unroll
            for (int i = 0; i < 4; ++i) {
                MMA_BF16(acc[i][0], a[i], b[0][0], b[0][1]);
                MMA_BF16(acc[i][1], a[i], b[0][2], b[0][3]);
                MMA_BF16(acc[i][2], a[i], b[1][0], b[1][1]);
                MMA_BF16(acc[i][3], a[i], b[1][2], b[1][3]);
            }
        }
        __syncthreads();
    }

    // ---- epilogue: bias add + store + fused BN stats ----
    float* s_sum = (float*)smem;     // [128]
    float* s_sq  = s_sum + 128;      // [128]
    if (tid < 128) { s_sum[tid] = 0.f; s_sq[tid] = 0.f; }
    __syncthreads();

    int g = lane >> 2, t = lane & 3;
    #pragma unroll
    for (int f = 0; f < 4; ++f) {
        int col = wn + f * 8 + t * 2;
        float bx = __ldg(bias + col), by = __ldg(bias + col + 1);
        float ls0 = 0.f, lq0 = 0.f, ls1 = 0.f, lq1 = 0.f;
        #pragma unroll
        for (int i = 0; i < 4; ++i) {
            int r0 = m0 + wm + i * 16 + g;
            if (r0 < n) {
                float y0 = acc[i][f][0] + bx, y1 = acc[i][f][1] + by;
                *(float2*)(C + (size_t)r0 * 128 + col) = make_float2(y0, y1);
                ls0 += y0; lq0 += y0 * y0; ls1 += y1; lq1 += y1 * y1;
            }
            int r1 = r0 + 8;
            if (r1 < n) {
                float y0 = acc[i][f][2] + bx, y1 = acc[i][f][3] + by;
                *(float2*)(C + (size_t)r1 * 128 + col) = make_float2(y0, y1);
                ls0 += y0; lq0 += y0 * y0; ls1 += y1; lq1 += y1 * y1;
            }
        }
        atomicAdd(&s_sum[col], ls0); atomicAdd(&s_sq[col], lq0);
        atomicAdd(&s_sum[col + 1], ls1); atomicAdd(&s_sq[col + 1], lq1);
    }
    __syncthreads();
    if (tid < 128) {
        atomicAdd(&g_sums[slot * 128 + tid], s_sum[tid]);
        atomicAdd(&g_sumsq[slot * 128 + tid], s_sq[tid]);
    }
}

// ------------------- BN post: planes and/or fp32 out -------------------
__global__ void k_bn_post(const float* __restrict__ pre,
                          const float* __restrict__ gamma,
                          const float* __restrict__ beta,
                          float* __restrict__ out,
                          __nv_bfloat16* __restrict__ phi,
                          __nv_bfloat16* __restrict__ plo,
                          int slot, int relu, float invN, int n) {
    int idx = blockIdx.x * blockDim.x + threadIdx.x;
    if (idx >= n * 32) return;
    int c4 = (idx & 31) * 4;
    float4 v = ((const float4*)pre)[idx];
    float y[4];
    #pragma unroll
    for (int j = 0; j < 4; j++) {
        int c = c4 + j;
        float mu = g_sums[slot * 128 + c] * invN;
        float var = g_sumsq[slot * 128 + c] * invN - mu * mu;
        float sc = __ldg(gamma + c) * rsqrtf(var + EPS);
        float be = __ldg(beta + c);
        float x = (j == 0) ? v.x : (j == 1) ? v.y : (j == 2) ? v.z : v.w;
        float yy = (x - mu) * sc + be;
        if (relu) yy = fmaxf(yy, 0.f);
        y[j] = yy;
    }
    if (out) ((float4*)out)[idx] = make_float4(y[0], y[1], y[2], y[3]);
    if (phi) {
        uint32_t h01, l01, h23, l23;
        split2(y[0], y[1], h01, l01);
        split2(y[2], y[3], h23, l23);
        ((uint2*)phi)[idx] = make_uint2(h01, h23);
        ((uint2*)plo)[idx] = make_uint2(l01, l23);
    }
}

// ------------------- launcher -------------------
extern "C" void kernel_launch(void* const* d_in, const int* in_sizes, int n_in,
                              void* d_out, int out_size) {
    const float* x     = (const float*)d_in[0];
    const int*   src   = (const int*)d_in[1];
    const int*   dst   = (const int*)d_in[2];
    const int*   ety   = (const int*)d_in[3];
    const float* W0    = (const float*)d_in[4];
    const float* loop0 = (const float*)d_in[5];
    const float* b0    = (const float*)d_in[6];
    const float* g0    = (const float*)d_in[7];
    const float* be0   = (const float*)d_in[8];
    const float* Ws    = (const float*)d_in[9];
    const float* loops = (const float*)d_in[10];
    const float* bs    = (const float*)d_in[11];
    const float* gs    = (const float*)d_in[12];
    const float* bes   = (const float*)d_in[13];
    const float* Wl    = (const float*)d_in[14];
    const float* bl    = (const float*)d_in[15];
    const float* gl    = (const float*)d_in[16];
    const float* bel   = (const float*)d_in[17];

    int N = in_sizes[0] / 64;
    int E = in_sizes[1];
    float* out = (float*)d_out;
    float invN = 1.0f / (float)N;

    float* preP;
    __nv_bfloat16 *shiP, *sloP, *hhiP, *hloP, *wimgP;
    cudaGetSymbolAddress((void**)&preP, g_pre);
    cudaGetSymbolAddress((void**)&shiP, g_shi);
    cudaGetSymbolAddress((void**)&sloP, g_slo);
    cudaGetSymbolAddress((void**)&hhiP, g_hhi);
    cudaGetSymbolAddress((void**)&hloP, g_hlo);
    cudaGetSymbolAddress((void**)&wimgP, g_wimg);

    cudaFuncSetAttribute(k_gemm_mma, cudaFuncAttributeMaxDynamicSharedMemorySize, GEMM_SMEM);

    int tb = 256;
    int gE = (E + tb - 1) / tb;
    int nb = (N + 255) / 256;
    int gW = (N * 32 + tb - 1) / tb;
    int gG = (N + 127) / 128;
    int gV = (N * 32 + tb - 1) / tb;

    // --- fused preprocessing: cursor/stats zero + weight images + x planes ---
    int nbP = nb;
    int nbW = (54 * 2048 + 255) / 256;
    int nbX = (N * 16 + 255) / 256;
    k_pre_all<<<nbP + nbW + nbX, tb>>>(x, W0, loop0, Ws, loops, Wl, N, nbP, nbW);

    // --- CSR build (by dst), parallel scan ---
    k_hist<<<gE, tb>>>(dst, E);
    k_scan1<<<nb, 256>>>(N);
    k_scan3<<<nb, 256>>>(N);
    k_fill<<<gE, tb>>>(src, dst, ety, E);

    // --- layer 0: K = 256 (agg) + 64 (x planes), stats slot 0 ---
    k_agg64<<<gW, tb>>>(x, N);
    k_gemm_mma<<<gG, tb, GEMM_SMEM>>>((const char*)shiP, (const char*)sloP, 256,
                                      (const char*)hhiP, (const char*)hloP, 64,
                                      (const char*)wimgP, b0, preP, N, 0);

    // --- hidden layers: K = 512 + 128, stats slots 1,2 (BN fused into agg) ---
    for (int l = 0; l < 2; l++) {
        const float* gm = (l == 0) ? g0 : gs + (l - 1) * 128;
        const float* bt = (l == 0) ? be0 : bes + (l - 1) * 128;
        k_agg128bn<<<gW, tb>>>(preP, gm, bt, l, invN, N);
        k_gemm_mma<<<gG, tb, GEMM_SMEM>>>((const char*)shiP, (const char*)sloP, 512,
                                          (const char*)hhiP, (const char*)hloP, 128,
                                          (const char*)wimgP + (size_t)(10 + l * 20) * 16384,
                                          bs + l * 128, preP, N, l + 1);
    }

    // --- final linear: K = 128 (h2 planes), stats slot 3 ---
    k_bn_post<<<gV, tb>>>(preP, gs + 128, bes + 128, (float*)nullptr, hhiP, hloP, 2, 1, invN, N);
    k_gemm_mma<<<gG, tb, GEMM_SMEM>>>((const char*)hhiP, (const char*)hloP, 128,
                                      (const char*)hhiP, (const char*)hloP, 0,
                                      (const char*)wimgP + (size_t)50 * 16384, bl, preP, N, 3);
    k_bn_post<<<gV, tb>>>(preP, gl, bel, out, (__nv_bfloat16*)nullptr, (__nv_bfloat16*)nullptr,
                          3, 0, invN, N);
}